// round 8
// baseline (speedup 1.0000x reference)
#include <cuda_runtime.h>
#include <cuda_fp16.h>
#include <cstdint>

#define NNODES 50000
#define NEDGES 600000

// ---------------- device scratch (no allocations allowed) ----------------
__device__ int   g_deg[NNODES];
__device__ int   g_off[NNODES + 1];
__device__ int   g_cur[NNODES];
__device__ int   g_srcsorted[NEDGES];

__device__ float g_h0[NNODES * 256];
__device__ float g_h1[NNODES * 256];
__device__ float g_part[NNODES * 256];   // fp32 partial (h @ Wr) per layer

// fp16 hi|lo split planes (stored as ushort bits)
__device__ unsigned short g_xs  [NNODES * 256];   // x split   [hi128|lo128]
__device__ unsigned short g_aggs[NNODES * 512];   // agg split [hi K |lo K]
__device__ unsigned short g_hsa [NNODES * 512];   // h0 split
__device__ unsigned short g_hsb [NNODES * 512];   // h1 split

// weight splits: W'' = [Whi ; Wlo], [2K, 256] row-major (rows = k)
__device__ unsigned short g_Wl0s[256 * 256];
__device__ unsigned short g_Wr0s[256 * 256];
__device__ unsigned short g_Wl1s[512 * 256];
__device__ unsigned short g_Wr1s[512 * 256];
__device__ unsigned short g_Wl2s[512 * 256];
__device__ unsigned short g_Wr2s[512 * 256];

// ---------------- helpers ----------------
__device__ __forceinline__ unsigned short hfbits(float f) {
    __half h = __float2half_rn(f);
    return reinterpret_cast<unsigned short&>(h);
}
__device__ __forceinline__ float hffloat(unsigned short u) {
    __half h;
    reinterpret_cast<unsigned short&>(h) = u;
    return __half2float(h);
}
__device__ __forceinline__ uint32_t smem_u32(const void* p) {
    return (uint32_t)__cvta_generic_to_shared(p);
}
__device__ __forceinline__ void cp16(uint32_t dst, const void* src, int sz) {
    asm volatile("cp.async.cg.shared.global [%0], [%1], 16, %2;\n"
                 :: "r"(dst), "l"(src), "r"(sz));
}
__device__ __forceinline__ void cp_commit() {
    asm volatile("cp.async.commit_group;\n" ::: "memory");
}

#define LDSM4(R0, R1, R2, R3, ADDR) \
    asm volatile("ldmatrix.sync.aligned.m8n8.x4.shared.b16 {%0,%1,%2,%3}, [%4];" \
                 : "=r"(R0), "=r"(R1), "=r"(R2), "=r"(R3) : "r"(ADDR))
#define LDSM4T(R0, R1, R2, R3, ADDR) \
    asm volatile("ldmatrix.sync.aligned.m8n8.x4.trans.shared.b16 {%0,%1,%2,%3}, [%4];" \
                 : "=r"(R0), "=r"(R1), "=r"(R2), "=r"(R3) : "r"(ADDR))
#define MMA16816(D, A, B) \
    asm volatile("mma.sync.aligned.m16n8k16.row.col.f32.f16.f16.f32 " \
                 "{%0,%1,%2,%3},{%4,%5,%6,%7},{%8,%9},{%0,%1,%2,%3};" \
                 : "+f"((D)[0]), "+f"((D)[1]), "+f"((D)[2]), "+f"((D)[3]) \
                 : "r"((A)[0]), "r"((A)[1]), "r"((A)[2]), "r"((A)[3]), \
                   "r"((B)[0]), "r"((B)[1]))

// ---------------- CSR build ----------------
__global__ void zero_deg_kernel() {
    int i = blockIdx.x * blockDim.x + threadIdx.x;
    if (i < NNODES) g_deg[i] = 0;
}
__global__ void hist_kernel(const int* __restrict__ dst) {
    int e = blockIdx.x * blockDim.x + threadIdx.x;
    if (e < NEDGES) atomicAdd(&g_deg[dst[e]], 1);
}
__global__ void scan_kernel() {
    __shared__ int sums[1024];
    int t = threadIdx.x;
    const int n = NNODES;
    const int chunk = (n + 1023) / 1024;
    int begin = t * chunk;
    int end = begin + chunk; if (end > n) end = n;
    int s = 0;
    for (int i = begin; i < end; ++i) s += g_deg[i];
    sums[t] = s;
    __syncthreads();
    for (int ofs = 1; ofs < 1024; ofs <<= 1) {
        int v = (t >= ofs) ? sums[t - ofs] : 0;
        __syncthreads();
        sums[t] += v;
        __syncthreads();
    }
    int prefix = (t == 0) ? 0 : sums[t - 1];
    for (int i = begin; i < end; ++i) {
        g_off[i] = prefix;
        g_cur[i] = prefix;
        prefix += g_deg[i];
    }
    if (t == 1023) g_off[n] = NEDGES;
}
__global__ void fill_kernel(const int* __restrict__ src, const int* __restrict__ dst) {
    int e = blockIdx.x * blockDim.x + threadIdx.x;
    if (e < NEDGES) {
        int d = dst[e];
        int p = atomicAdd(&g_cur[d], 1);
        g_srcsorted[p] = src[e];
    }
}

// ---------------- conversion kernels ----------------
__global__ void xsplit_kernel(const float* __restrict__ x, unsigned short* __restrict__ out) {
    int i = blockIdx.x * blockDim.x + threadIdx.x;
    if (i >= NNODES * 128) return;
    int r = i >> 7, c = i & 127;
    float f = x[i];
    unsigned short hb = hfbits(f);
    out[r * 256 + c] = hb;
    out[r * 256 + 128 + c] = hfbits(f - hffloat(hb));
}
// W [K,256] row-major -> out [2K, 256]: rows [0,K)=hi, [K,2K)=lo
__global__ void wsplit_kernel(const float* __restrict__ W, unsigned short* __restrict__ out, int K) {
    int i = blockIdx.x * blockDim.x + threadIdx.x;
    int total = 2 * K * 256;
    if (i >= total) return;
    int r = i >> 8, c = i & 255;
    if (r < K) {
        out[i] = hfbits(W[r * 256 + c]);
    } else {
        float f = W[(r - K) * 256 + c];
        unsigned short hb = hfbits(f);
        out[i] = hfbits(f - hffloat(hb));
    }
}

// ---------------- gather-mean aggregation, fp16-split output ----------------
__device__ __forceinline__ void split_store4(float4 v, unsigned short* hip, unsigned short* lop) {
    unsigned short h0 = hfbits(v.x), h1 = hfbits(v.y), h2 = hfbits(v.z), h3 = hfbits(v.w);
    uint2 hi = make_uint2((uint32_t)h0 | ((uint32_t)h1 << 16),
                          (uint32_t)h2 | ((uint32_t)h3 << 16));
    *(uint2*)hip = hi;
    unsigned short l0 = hfbits(v.x - hffloat(h0));
    unsigned short l1 = hfbits(v.y - hffloat(h1));
    unsigned short l2 = hfbits(v.z - hffloat(h2));
    unsigned short l3 = hfbits(v.w - hffloat(h3));
    uint2 lo = make_uint2((uint32_t)l0 | ((uint32_t)l1 << 16),
                          (uint32_t)l2 | ((uint32_t)l3 << 16));
    *(uint2*)lop = lo;
}

template <int D>
__global__ void agg_split_kernel(const float* __restrict__ h, unsigned short* __restrict__ outs) {
    int warp = (blockIdx.x * blockDim.x + threadIdx.x) >> 5;
    if (warp >= NNODES) return;
    int lane = threadIdx.x & 31;
    int s = g_off[warp];
    int e = g_off[warp + 1];
    int cnt = e - s;
    float inv = 1.0f / (float)(cnt > 0 ? cnt : 1);
    int c0 = lane * 4;
    unsigned short* orow = outs + (size_t)warp * (2 * D);

    if (D == 128) {
        float4 acc = make_float4(0.f, 0.f, 0.f, 0.f);
        for (int i = s; i < e; ++i) {
            int src = g_srcsorted[i];
            float4 v = *(const float4*)&h[(size_t)src * 128 + c0];
            acc.x += v.x; acc.y += v.y; acc.z += v.z; acc.w += v.w;
        }
        acc.x *= inv; acc.y *= inv; acc.z *= inv; acc.w *= inv;
        split_store4(acc, orow + c0, orow + 128 + c0);
    } else {
        float4 a0 = make_float4(0.f, 0.f, 0.f, 0.f);
        float4 a1 = make_float4(0.f, 0.f, 0.f, 0.f);
        for (int i = s; i < e; ++i) {
            int src = g_srcsorted[i];
            const float* row = &h[(size_t)src * 256];
            float4 v0 = *(const float4*)&row[c0];
            float4 v1 = *(const float4*)&row[c0 + 128];
            a0.x += v0.x; a0.y += v0.y; a0.z += v0.z; a0.w += v0.w;
            a1.x += v1.x; a1.y += v1.y; a1.z += v1.z; a1.w += v1.w;
        }
        a0.x *= inv; a0.y *= inv; a0.z *= inv; a0.w *= inv;
        a1.x *= inv; a1.y *= inv; a1.z *= inv; a1.w *= inv;
        split_store4(a0, orow + c0, orow + 256 + c0);
        split_store4(a1, orow + 128 + c0, orow + 256 + 128 + c0);
    }
}

// ---------------- fp16 MMA GEMM, single-operand-pair, split-term schedule ----------------
// A planes: [M, 2Kp] fp16 (cols [0,Kp)=hi, [Kp,2Kp)=lo).
// B'' = [2Kp, 256] fp16 (rows [0,Kp)=hi, [Kp,2Kp)=lo).
// Chunks kb = 0..cpp*32:
//   kb in [0,Kp):     Ahi*Bhi   kb in [Kp,2Kp): Alo*Bhi   kb in [2Kp,3Kp): Ahi*Blo
// cpp = 2*Kp/32 -> 2-term; cpp = 3*Kp/32 -> 3-term.
// Epilogue: v = acc (+bias) (+partial); relu opt; writes Cout fp32 and/or Csplit planes.
__global__ void __launch_bounds__(256, 2)
gemm_mma_kernel(const unsigned short* __restrict__ A,
                int Kp, int cpp,
                const unsigned short* __restrict__ B,
                const float* __restrict__ bias,
                const float* __restrict__ partial,
                float* __restrict__ Cout,
                unsigned short* __restrict__ Csplit,
                int relu) {
    constexpr int AP = 40;    // As row pad (fp16 elems)
    constexpr int BP = 136;   // Bs row pad
    __shared__ unsigned short As[2][128 * AP];
    __shared__ unsigned short Bs[2][32 * BP];

    const int tid = threadIdx.x;
    const int warp = tid >> 5;
    const int lane = tid & 31;
    const int warp_m = warp & 3;   // 4 warps of 32 rows
    const int warp_n = warp >> 2;  // 2 warps of 64 cols
    const int m0 = blockIdx.y * 128;
    const int n0 = blockIdx.x * 128;

    const int astride = 2 * Kp;
    const int nchunks = cpp;

    float acc[2][8][4];
#pragma unroll
    for (int mt = 0; mt < 2; ++mt)
#pragma unroll
        for (int nt = 0; nt < 8; ++nt)
#pragma unroll
            for (int q = 0; q < 4; ++q) acc[mt][nt][q] = 0.f;

    uint32_t as_base[2] = { smem_u32(&As[0][0]), smem_u32(&As[1][0]) };
    uint32_t bs_base[2] = { smem_u32(&Bs[0][0]), smem_u32(&Bs[1][0]) };

    // ---- tile loader ----
    auto load_tile = [&](int c, int buf) {
        int kb = c << 5;
        int acol = (kb < 2 * Kp) ? kb : kb - 2 * Kp;
        int brow = (kb < Kp) ? kb : kb - Kp;
        // A tile: 128 rows x 32 cols
        {
            int r = tid >> 2;
            int kc = (tid & 3) << 3;
#pragma unroll
            for (int i = 0; i < 2; ++i) {
                int row = r + i * 64;
                int grow = m0 + row;
                int ok = grow < NNODES;
                const unsigned short* src = A + (size_t)(ok ? grow : 0) * astride + acol + kc;
                cp16(as_base[buf] + (row * AP + kc) * 2, src, ok ? 16 : 0);
            }
        }
        // B tile: 32 rows x 128 cols
        {
            int r = tid >> 4;
            int col = (tid & 15) << 3;
#pragma unroll
            for (int i = 0; i < 2; ++i) {
                int row = r + i * 16;
                const unsigned short* src = B + (size_t)(brow + row) * 256 + n0 + col;
                cp16(bs_base[buf] + (row * BP + col) * 2, src, 16);
            }
        }
        cp_commit();
    };

    load_tile(0, 0);

    for (int c = 0; c < nchunks; ++c) {
        if (c + 1 < nchunks) {
            load_tile(c + 1, (c + 1) & 1);
            asm volatile("cp.async.wait_group 1;\n" ::: "memory");
        } else {
            asm volatile("cp.async.wait_group 0;\n" ::: "memory");
        }
        __syncthreads();

        int buf = c & 1;
        uint32_t ab = as_base[buf];
        uint32_t bb = bs_base[buf];
#pragma unroll
        for (int k16 = 0; k16 < 32; k16 += 16) {
            uint32_t a[2][4];
#pragma unroll
            for (int mt = 0; mt < 2; ++mt) {
                int mrow = warp_m * 32 + mt * 16 + (lane & 15);
                int kc = k16 + ((lane >> 4) << 3);
                LDSM4(a[mt][0], a[mt][1], a[mt][2], a[mt][3], ab + (mrow * AP + kc) * 2);
            }
            uint32_t b[8][2];
#pragma unroll
            for (int p = 0; p < 4; ++p) {
                int brow2 = k16 + (lane & 15);
                int bcol = warp_n * 64 + p * 16 + ((lane >> 4) << 3);
                LDSM4T(b[2 * p][0], b[2 * p][1], b[2 * p + 1][0], b[2 * p + 1][1],
                       bb + (brow2 * BP + bcol) * 2);
            }
#pragma unroll
            for (int mt = 0; mt < 2; ++mt)
#pragma unroll
                for (int nt = 0; nt < 8; ++nt)
                    MMA16816(acc[mt][nt], a[mt], b[nt]);
        }
        __syncthreads();
    }

    // ---- epilogue ----
    int g = lane >> 2;
    int tg = lane & 3;
#pragma unroll
    for (int mt = 0; mt < 2; ++mt) {
#pragma unroll
        for (int nt = 0; nt < 8; ++nt) {
            int col = n0 + warp_n * 64 + nt * 8 + tg * 2;
            float b0 = 0.f, b1 = 0.f;
            if (bias) { b0 = bias[col]; b1 = bias[col + 1]; }
            int r0 = m0 + warp_m * 32 + mt * 16 + g;
            int r1 = r0 + 8;
            float v0 = acc[mt][nt][0] + b0;
            float v1 = acc[mt][nt][1] + b1;
            float v2 = acc[mt][nt][2] + b0;
            float v3 = acc[mt][nt][3] + b1;
            if (partial) {
                if (r0 < NNODES) {
                    float2 p = *(const float2*)&partial[(size_t)r0 * 256 + col];
                    v0 += p.x; v1 += p.y;
                }
                if (r1 < NNODES) {
                    float2 p = *(const float2*)&partial[(size_t)r1 * 256 + col];
                    v2 += p.x; v3 += p.y;
                }
            }
            if (relu) {
                v0 = v0 > 0.f ? v0 : 0.f;
                v1 = v1 > 0.f ? v1 : 0.f;
                v2 = v2 > 0.f ? v2 : 0.f;
                v3 = v3 > 0.f ? v3 : 0.f;
            }
            if (r0 < NNODES) {
                if (Cout) *(float2*)&Cout[(size_t)r0 * 256 + col] = make_float2(v0, v1);
                if (Csplit) {
                    unsigned short h0 = hfbits(v0), h1 = hfbits(v1);
                    *(uint32_t*)&Csplit[(size_t)r0 * 512 + col] =
                        (uint32_t)h0 | ((uint32_t)h1 << 16);
                    unsigned short l0 = hfbits(v0 - hffloat(h0));
                    unsigned short l1 = hfbits(v1 - hffloat(h1));
                    *(uint32_t*)&Csplit[(size_t)r0 * 512 + 256 + col] =
                        (uint32_t)l0 | ((uint32_t)l1 << 16);
                }
            }
            if (r1 < NNODES) {
                if (Cout) *(float2*)&Cout[(size_t)r1 * 256 + col] = make_float2(v2, v3);
                if (Csplit) {
                    unsigned short h2 = hfbits(v2), h3 = hfbits(v3);
                    *(uint32_t*)&Csplit[(size_t)r1 * 512 + col] =
                        (uint32_t)h2 | ((uint32_t)h3 << 16);
                    unsigned short l2 = hfbits(v2 - hffloat(h2));
                    unsigned short l3 = hfbits(v3 - hffloat(h3));
                    *(uint32_t*)&Csplit[(size_t)r1 * 512 + 256 + col] =
                        (uint32_t)l2 | ((uint32_t)l3 << 16);
                }
            }
        }
    }
}

// ---------------- launch ----------------
extern "C" void kernel_launch(void* const* d_in, const int* in_sizes, int n_in,
                              void* d_out, int out_size) {
    const float* x   = (const float*)d_in[0];
    const int*   ei  = (const int*)d_in[1];
    const float* Wl0 = (const float*)d_in[2];
    const float* bl0 = (const float*)d_in[3];
    const float* Wr0 = (const float*)d_in[4];
    const float* Wl1 = (const float*)d_in[5];
    const float* bl1 = (const float*)d_in[6];
    const float* Wr1 = (const float*)d_in[7];
    const float* Wl2 = (const float*)d_in[8];
    const float* bl2 = (const float*)d_in[9];
    const float* Wr2 = (const float*)d_in[10];
    float* out = (float*)d_out;

    const int* src = ei;
    const int* dst = ei + NEDGES;

    float *h0p, *h1p, *partp;
    unsigned short *xsp, *aggsp, *hsap, *hsbp;
    unsigned short *wl0p, *wr0p, *wl1p, *wr1p, *wl2p, *wr2p;
    cudaGetSymbolAddress((void**)&h0p, g_h0);
    cudaGetSymbolAddress((void**)&h1p, g_h1);
    cudaGetSymbolAddress((void**)&partp, g_part);
    cudaGetSymbolAddress((void**)&xsp, g_xs);
    cudaGetSymbolAddress((void**)&aggsp, g_aggs);
    cudaGetSymbolAddress((void**)&hsap, g_hsa);
    cudaGetSymbolAddress((void**)&hsbp, g_hsb);
    cudaGetSymbolAddress((void**)&wl0p, g_Wl0s);
    cudaGetSymbolAddress((void**)&wr0p, g_Wr0s);
    cudaGetSymbolAddress((void**)&wl1p, g_Wl1s);
    cudaGetSymbolAddress((void**)&wr1p, g_Wr1s);
    cudaGetSymbolAddress((void**)&wl2p, g_Wl2s);
    cudaGetSymbolAddress((void**)&wr2p, g_Wr2s);

    // lazy-created side stream + events (created on the uncaptured correctness call)
    static cudaStream_t s2 = nullptr;
    static cudaEvent_t evRoot = nullptr, evW, evH0, evP1, evH1, evP2;
    if (!s2) {
        cudaStreamCreateWithFlags(&s2, cudaStreamNonBlocking);
        cudaEventCreateWithFlags(&evRoot, cudaEventDisableTiming);
        cudaEventCreateWithFlags(&evW,    cudaEventDisableTiming);
        cudaEventCreateWithFlags(&evH0,   cudaEventDisableTiming);
        cudaEventCreateWithFlags(&evP1,   cudaEventDisableTiming);
        cudaEventCreateWithFlags(&evH1,   cudaEventDisableTiming);
        cudaEventCreateWithFlags(&evP2,   cudaEventDisableTiming);
    }

    dim3 gemm_grid(2, (NNODES + 127) / 128);
    int agg_blocks = (NNODES * 32 + 255) / 256;

    // ---- capture-legal fork: root event on the capture stream, s2 waits on it ----
    cudaEventRecord(evRoot, 0);
    cudaStreamWaitEvent(s2, evRoot, 0);

    // ---- stream 0: CSR build ----
    zero_deg_kernel<<<(NNODES + 255) / 256, 256>>>();
    hist_kernel<<<(NEDGES + 255) / 256, 256>>>(dst);
    scan_kernel<<<1, 1024>>>();
    fill_kernel<<<(NEDGES + 255) / 256, 256>>>(src, dst);

    // ---- stream s2 (forked from evRoot): conversions + layer-0 Wr pass ----
    xsplit_kernel<<<(NNODES * 128 + 255) / 256, 256, 0, s2>>>(x, xsp);
    wsplit_kernel<<<(2 * 128 * 256 + 255) / 256, 256, 0, s2>>>(Wl0, wl0p, 128);
    wsplit_kernel<<<(2 * 128 * 256 + 255) / 256, 256, 0, s2>>>(Wr0, wr0p, 128);
    wsplit_kernel<<<(2 * 256 * 256 + 255) / 256, 256, 0, s2>>>(Wl1, wl1p, 256);
    wsplit_kernel<<<(2 * 256 * 256 + 255) / 256, 256, 0, s2>>>(Wr1, wr1p, 256);
    wsplit_kernel<<<(2 * 256 * 256 + 255) / 256, 256, 0, s2>>>(Wl2, wl2p, 256);
    wsplit_kernel<<<(2 * 256 * 256 + 255) / 256, 256, 0, s2>>>(Wr2, wr2p, 256);
    // L0 Wr pass: 3-term (cpp = 3*128/32 = 12), x'' @ Wr0'' -> partial
    gemm_mma_kernel<<<gemm_grid, 256, 0, s2>>>(xsp, 128, 12, wr0p,
                                               nullptr, nullptr, partp, nullptr, 0);
    cudaEventRecord(evW, s2);

    // ---- stream 0: layer-0 agg, then join + final ----
    agg_split_kernel<128><<<agg_blocks, 256>>>(x, aggsp);
    cudaStreamWaitEvent(0, evW, 0);
    // L0 Wl final: 3-term, + partial + bias, relu, writes h0 fp32 + split
    gemm_mma_kernel<<<gemm_grid, 256>>>(aggsp, 128, 12, wl0p,
                                        bl0, partp, h0p, hsap, 1);
    cudaEventRecord(evH0, 0);

    // ---- layer 1 ----
    cudaStreamWaitEvent(s2, evH0, 0);
    gemm_mma_kernel<<<gemm_grid, 256, 0, s2>>>(hsap, 256, 16, wr1p,
                                               nullptr, nullptr, partp, nullptr, 0);
    cudaEventRecord(evP1, s2);
    agg_split_kernel<256><<<agg_blocks, 256>>>(h0p, aggsp);
    cudaStreamWaitEvent(0, evP1, 0);
    gemm_mma_kernel<<<gemm_grid, 256>>>(aggsp, 256, 16, wl1p,
                                        bl1, partp, h1p, hsbp, 1);
    cudaEventRecord(evH1, 0);

    // ---- layer 2 ----
    cudaStreamWaitEvent(s2, evH1, 0);
    gemm_mma_kernel<<<gemm_grid, 256, 0, s2>>>(hsbp, 256, 16, wr2p,
                                               nullptr, nullptr, partp, nullptr, 0);
    cudaEventRecord(evP2, s2);
    agg_split_kernel<256><<<agg_blocks, 256>>>(h1p, aggsp);
    cudaStreamWaitEvent(0, evP2, 0);
    gemm_mma_kernel<<<gemm_grid, 256>>>(aggsp, 256, 16, wl2p,
                                        bl2, partp, out, nullptr, 0);
}

// round 11
// speedup vs baseline: 1.1279x; 1.1279x over previous
#include <cuda_runtime.h>
#include <cuda_fp16.h>
#include <cstdint>

#define NNODES 50000
#define NEDGES 600000

// ---------------- device scratch (no allocations allowed) ----------------
__device__ int   g_deg[NNODES];
__device__ int   g_off[NNODES + 1];
__device__ int   g_cur[NNODES];
__device__ int   g_srcsorted[NEDGES];

// fp16 hi|lo split planes (stored as ushort bits)
__device__ unsigned short g_xs  [NNODES * 256];   // x split   [hi128|lo128]
__device__ unsigned short g_aggs[NNODES * 512];   // agg split [hi K |lo K]
__device__ unsigned short g_hsa [NNODES * 512];   // h0 split
__device__ unsigned short g_hsb [NNODES * 512];   // h1 split

// weight splits: W'' = [Whi ; Wlo], [2K, 256] row-major (rows = k)
__device__ unsigned short g_Wl0s[256 * 256];
__device__ unsigned short g_Wr0s[256 * 256];
__device__ unsigned short g_Wl1s[512 * 256];
__device__ unsigned short g_Wr1s[512 * 256];
__device__ unsigned short g_Wl2s[512 * 256];
__device__ unsigned short g_Wr2s[512 * 256];

// ---------------- helpers ----------------
__device__ __forceinline__ unsigned short hfbits(float f) {
    __half h = __float2half_rn(f);
    return reinterpret_cast<unsigned short&>(h);
}
__device__ __forceinline__ float hffloat(unsigned short u) {
    __half h;
    reinterpret_cast<unsigned short&>(h) = u;
    return __half2float(h);
}
__device__ __forceinline__ uint32_t smem_u32(const void* p) {
    return (uint32_t)__cvta_generic_to_shared(p);
}
__device__ __forceinline__ void cp16(uint32_t dst, const void* src, int sz) {
    asm volatile("cp.async.cg.shared.global [%0], [%1], 16, %2;\n"
                 :: "r"(dst), "l"(src), "r"(sz));
}
__device__ __forceinline__ void cp_commit() {
    asm volatile("cp.async.commit_group;\n" ::: "memory");
}

#define LDSM4(R0, R1, R2, R3, ADDR) \
    asm volatile("ldmatrix.sync.aligned.m8n8.x4.shared.b16 {%0,%1,%2,%3}, [%4];" \
                 : "=r"(R0), "=r"(R1), "=r"(R2), "=r"(R3) : "r"(ADDR))
#define LDSM4T(R0, R1, R2, R3, ADDR) \
    asm volatile("ldmatrix.sync.aligned.m8n8.x4.trans.shared.b16 {%0,%1,%2,%3}, [%4];" \
                 : "=r"(R0), "=r"(R1), "=r"(R2), "=r"(R3) : "r"(ADDR))
#define MMA16816(D, A, B) \
    asm volatile("mma.sync.aligned.m16n8k16.row.col.f32.f16.f16.f32 " \
                 "{%0,%1,%2,%3},{%4,%5,%6,%7},{%8,%9},{%0,%1,%2,%3};" \
                 : "+f"((D)[0]), "+f"((D)[1]), "+f"((D)[2]), "+f"((D)[3]) \
                 : "r"((A)[0]), "r"((A)[1]), "r"((A)[2]), "r"((A)[3]), \
                   "r"((B)[0]), "r"((B)[1]))

// ---------------- CSR build ----------------
__global__ void zero_deg_kernel() {
    int i = blockIdx.x * blockDim.x + threadIdx.x;
    if (i < NNODES) g_deg[i] = 0;
}
__global__ void hist_kernel(const int* __restrict__ dst) {
    int e = blockIdx.x * blockDim.x + threadIdx.x;
    if (e < NEDGES) atomicAdd(&g_deg[dst[e]], 1);
}
__global__ void scan_kernel() {
    __shared__ int sums[1024];
    int t = threadIdx.x;
    const int n = NNODES;
    const int chunk = (n + 1023) / 1024;
    int begin = t * chunk;
    int end = begin + chunk; if (end > n) end = n;
    int s = 0;
    for (int i = begin; i < end; ++i) s += g_deg[i];
    sums[t] = s;
    __syncthreads();
    for (int ofs = 1; ofs < 1024; ofs <<= 1) {
        int v = (t >= ofs) ? sums[t - ofs] : 0;
        __syncthreads();
        sums[t] += v;
        __syncthreads();
    }
    int prefix = (t == 0) ? 0 : sums[t - 1];
    for (int i = begin; i < end; ++i) {
        g_off[i] = prefix;
        g_cur[i] = prefix;
        prefix += g_deg[i];
    }
    if (t == 1023) g_off[n] = NEDGES;
}
__global__ void fill_kernel(const int* __restrict__ src, const int* __restrict__ dst) {
    int e = blockIdx.x * blockDim.x + threadIdx.x;
    if (e < NEDGES) {
        int d = dst[e];
        int p = atomicAdd(&g_cur[d], 1);
        g_srcsorted[p] = src[e];
    }
}

// ---------------- conversion kernels ----------------
__global__ void xsplit_kernel(const float* __restrict__ x, unsigned short* __restrict__ out) {
    int i = blockIdx.x * blockDim.x + threadIdx.x;
    if (i >= NNODES * 128) return;
    int r = i >> 7, c = i & 127;
    float f = x[i];
    unsigned short hb = hfbits(f);
    out[r * 256 + c] = hb;
    out[r * 256 + 128 + c] = hfbits(f - hffloat(hb));
}
// W [K,256] row-major -> out [2K, 256]: rows [0,K)=hi, [K,2K)=lo
__global__ void wsplit_kernel(const float* __restrict__ W, unsigned short* __restrict__ out, int K) {
    int i = blockIdx.x * blockDim.x + threadIdx.x;
    int total = 2 * K * 256;
    if (i >= total) return;
    int r = i >> 8, c = i & 255;
    if (r < K) {
        out[i] = hfbits(W[r * 256 + c]);
    } else {
        float f = W[(r - K) * 256 + c];
        unsigned short hb = hfbits(f);
        out[i] = hfbits(f - hffloat(hb));
    }
}

// ---------------- aggregation ----------------
__device__ __forceinline__ void split_store4(float4 v, unsigned short* hip, unsigned short* lop) {
    unsigned short h0 = hfbits(v.x), h1 = hfbits(v.y), h2 = hfbits(v.z), h3 = hfbits(v.w);
    uint2 hi = make_uint2((uint32_t)h0 | ((uint32_t)h1 << 16),
                          (uint32_t)h2 | ((uint32_t)h3 << 16));
    *(uint2*)hip = hi;
    unsigned short l0 = hfbits(v.x - hffloat(h0));
    unsigned short l1 = hfbits(v.y - hffloat(h1));
    unsigned short l2 = hfbits(v.z - hffloat(h2));
    unsigned short l3 = hfbits(v.w - hffloat(h3));
    uint2 lo = make_uint2((uint32_t)l0 | ((uint32_t)l1 << 16),
                          (uint32_t)l2 | ((uint32_t)l3 << 16));
    *(uint2*)lop = lo;
}

// layer 0: gather fp32 x (D=128)
__global__ void agg_split_f32_kernel(const float* __restrict__ h, unsigned short* __restrict__ outs) {
    int warp = (blockIdx.x * blockDim.x + threadIdx.x) >> 5;
    if (warp >= NNODES) return;
    int lane = threadIdx.x & 31;
    int s = g_off[warp];
    int e = g_off[warp + 1];
    int cnt = e - s;
    float inv = 1.0f / (float)(cnt > 0 ? cnt : 1);
    int c0 = lane * 4;
    unsigned short* orow = outs + (size_t)warp * 256;

    float4 acc = make_float4(0.f, 0.f, 0.f, 0.f);
    for (int i = s; i < e; ++i) {
        int src = g_srcsorted[i];
        float4 v = *(const float4*)&h[(size_t)src * 128 + c0];
        acc.x += v.x; acc.y += v.y; acc.z += v.z; acc.w += v.w;
    }
    acc.x *= inv; acc.y *= inv; acc.z *= inv; acc.w *= inv;
    split_store4(acc, orow + c0, orow + 128 + c0);
}

// layers 1/2: gather fp16 hi plane of split buffer (D=256, row stride 512)
__global__ void agg_split_hi_kernel(const unsigned short* __restrict__ hs,
                                    unsigned short* __restrict__ outs) {
    int warp = (blockIdx.x * blockDim.x + threadIdx.x) >> 5;
    if (warp >= NNODES) return;
    int lane = threadIdx.x & 31;
    int s = g_off[warp];
    int e = g_off[warp + 1];
    int cnt = e - s;
    float inv = 1.0f / (float)(cnt > 0 ? cnt : 1);
    int c0 = lane * 4;
    unsigned short* orow = outs + (size_t)warp * 512;

    float4 a0 = make_float4(0.f, 0.f, 0.f, 0.f);
    float4 a1 = make_float4(0.f, 0.f, 0.f, 0.f);
    for (int i = s; i < e; ++i) {
        int src = g_srcsorted[i];
        const unsigned short* row = hs + (size_t)src * 512;
        uint2 u0 = *(const uint2*)&row[c0];
        uint2 u1 = *(const uint2*)&row[c0 + 128];
        __half2 p;
        float2 f;
        reinterpret_cast<uint32_t&>(p) = u0.x; f = __half22float2(p);
        a0.x += f.x; a0.y += f.y;
        reinterpret_cast<uint32_t&>(p) = u0.y; f = __half22float2(p);
        a0.z += f.x; a0.w += f.y;
        reinterpret_cast<uint32_t&>(p) = u1.x; f = __half22float2(p);
        a1.x += f.x; a1.y += f.y;
        reinterpret_cast<uint32_t&>(p) = u1.y; f = __half22float2(p);
        a1.z += f.x; a1.w += f.y;
    }
    a0.x *= inv; a0.y *= inv; a0.z *= inv; a0.w *= inv;
    a1.x *= inv; a1.y *= inv; a1.z *= inv; a1.w *= inv;
    split_store4(a0, orow + c0, orow + 256 + c0);
    split_store4(a1, orow + 128 + c0, orow + 256 + 128 + c0);
}

// ---------------- fused fp16 MMA GEMM (two passes), split-term schedule ----------------
// A planes: [M, 2Kp] fp16 (cols [0,Kp)=hi, [Kp,2Kp)=lo).
// B'' = [2Kp, 256] fp16 (rows [0,Kp)=hi, [Kp,2Kp)=lo).
// Within a pass, chunks kb = 0..cpp*32:
//   kb in [0,Kp):     Ahi*Bhi   kb in [Kp,2Kp): Alo*Bhi   kb in [2Kp,3Kp): Ahi*Blo
// cpp = 2*Kp/32 -> 2-term; cpp = 3*Kp/32 -> 3-term. nchunks = 2*cpp (pass0=A0/B0, pass1=A1/B1).
__global__ void __launch_bounds__(256, 2)
gemm_mma_kernel(const unsigned short* __restrict__ A0,
                const unsigned short* __restrict__ A1,
                int Kp, int cpp,
                const unsigned short* __restrict__ B0,
                const unsigned short* __restrict__ B1,
                const float* __restrict__ bias,
                float* __restrict__ Cout,
                unsigned short* __restrict__ Csplit,
                int relu) {
    constexpr int AP = 40;    // As row pad (fp16 elems)
    constexpr int BP = 136;   // Bs row pad
    __shared__ unsigned short As[2][128 * AP];
    __shared__ unsigned short Bs[2][32 * BP];

    const int tid = threadIdx.x;
    const int warp = tid >> 5;
    const int lane = tid & 31;
    const int warp_m = warp & 3;   // 4 warps of 32 rows
    const int warp_n = warp >> 2;  // 2 warps of 64 cols
    const int m0 = blockIdx.y * 128;
    const int n0 = blockIdx.x * 128;

    const int astride = 2 * Kp;
    const int nchunks = 2 * cpp;

    float acc[2][8][4];
#pragma unroll
    for (int mt = 0; mt < 2; ++mt)
#pragma unroll
        for (int nt = 0; nt < 8; ++nt)
#pragma unroll
            for (int q = 0; q < 4; ++q) acc[mt][nt][q] = 0.f;

    uint32_t as_base[2] = { smem_u32(&As[0][0]), smem_u32(&As[1][0]) };
    uint32_t bs_base[2] = { smem_u32(&Bs[0][0]), smem_u32(&Bs[1][0]) };

    // ---- tile loader ----
    auto load_tile = [&](int c, int buf) {
        int pass = (c >= cpp) ? 1 : 0;
        int kb = (c - pass * cpp) << 5;
        int acol = (kb < 2 * Kp) ? kb : kb - 2 * Kp;
        int brow = (kb < Kp) ? kb : kb - Kp;
        const unsigned short* A = pass ? A1 : A0;
        const unsigned short* B = pass ? B1 : B0;
        // A tile: 128 rows x 32 cols
        {
            int r = tid >> 2;
            int kc = (tid & 3) << 3;
#pragma unroll
            for (int i = 0; i < 2; ++i) {
                int row = r + i * 64;
                int grow = m0 + row;
                int ok = grow < NNODES;
                const unsigned short* src = A + (size_t)(ok ? grow : 0) * astride + acol + kc;
                cp16(as_base[buf] + (row * AP + kc) * 2, src, ok ? 16 : 0);
            }
        }
        // B tile: 32 rows x 128 cols
        {
            int r = tid >> 4;
            int col = (tid & 15) << 3;
#pragma unroll
            for (int i = 0; i < 2; ++i) {
                int row = r + i * 16;
                const unsigned short* src = B + (size_t)(brow + row) * 256 + n0 + col;
                cp16(bs_base[buf] + (row * BP + col) * 2, src, 16);
            }
        }
        cp_commit();
    };

    load_tile(0, 0);

    for (int c = 0; c < nchunks; ++c) {
        if (c + 1 < nchunks) {
            load_tile(c + 1, (c + 1) & 1);
            asm volatile("cp.async.wait_group 1;\n" ::: "memory");
        } else {
            asm volatile("cp.async.wait_group 0;\n" ::: "memory");
        }
        __syncthreads();

        int buf = c & 1;
        uint32_t ab = as_base[buf];
        uint32_t bb = bs_base[buf];
#pragma unroll
        for (int k16 = 0; k16 < 32; k16 += 16) {
            uint32_t a[2][4];
#pragma unroll
            for (int mt = 0; mt < 2; ++mt) {
                int mrow = warp_m * 32 + mt * 16 + (lane & 15);
                int kc = k16 + ((lane >> 4) << 3);
                LDSM4(a[mt][0], a[mt][1], a[mt][2], a[mt][3], ab + (mrow * AP + kc) * 2);
            }
            uint32_t b[8][2];
#pragma unroll
            for (int p = 0; p < 4; ++p) {
                int brow2 = k16 + (lane & 15);
                int bcol = warp_n * 64 + p * 16 + ((lane >> 4) << 3);
                LDSM4T(b[2 * p][0], b[2 * p][1], b[2 * p + 1][0], b[2 * p + 1][1],
                       bb + (brow2 * BP + bcol) * 2);
            }
#pragma unroll
            for (int mt = 0; mt < 2; ++mt)
#pragma unroll
                for (int nt = 0; nt < 8; ++nt)
                    MMA16816(acc[mt][nt], a[mt], b[nt]);
        }
        __syncthreads();
    }

    // ---- epilogue ----
    int g = lane >> 2;
    int tg = lane & 3;
#pragma unroll
    for (int mt = 0; mt < 2; ++mt) {
#pragma unroll
        for (int nt = 0; nt < 8; ++nt) {
            int col = n0 + warp_n * 64 + nt * 8 + tg * 2;
            float b0 = bias[col], b1 = bias[col + 1];
            int r0 = m0 + warp_m * 32 + mt * 16 + g;
            int r1 = r0 + 8;
            float v0 = acc[mt][nt][0] + b0;
            float v1 = acc[mt][nt][1] + b1;
            float v2 = acc[mt][nt][2] + b0;
            float v3 = acc[mt][nt][3] + b1;
            if (relu) {
                v0 = v0 > 0.f ? v0 : 0.f;
                v1 = v1 > 0.f ? v1 : 0.f;
                v2 = v2 > 0.f ? v2 : 0.f;
                v3 = v3 > 0.f ? v3 : 0.f;
            }
            if (r0 < NNODES) {
                if (Cout) *(float2*)&Cout[(size_t)r0 * 256 + col] = make_float2(v0, v1);
                if (Csplit) {
                    unsigned short h0 = hfbits(v0), h1 = hfbits(v1);
                    *(uint32_t*)&Csplit[(size_t)r0 * 512 + col] =
                        (uint32_t)h0 | ((uint32_t)h1 << 16);
                    unsigned short l0 = hfbits(v0 - hffloat(h0));
                    unsigned short l1 = hfbits(v1 - hffloat(h1));
                    *(uint32_t*)&Csplit[(size_t)r0 * 512 + 256 + col] =
                        (uint32_t)l0 | ((uint32_t)l1 << 16);
                }
            }
            if (r1 < NNODES) {
                if (Cout) *(float2*)&Cout[(size_t)r1 * 256 + col] = make_float2(v2, v3);
                if (Csplit) {
                    unsigned short h2 = hfbits(v2), h3 = hfbits(v3);
                    *(uint32_t*)&Csplit[(size_t)r1 * 512 + col] =
                        (uint32_t)h2 | ((uint32_t)h3 << 16);
                    unsigned short l2 = hfbits(v2 - hffloat(h2));
                    unsigned short l3 = hfbits(v3 - hffloat(h3));
                    *(uint32_t*)&Csplit[(size_t)r1 * 512 + 256 + col] =
                        (uint32_t)l2 | ((uint32_t)l3 << 16);
                }
            }
        }
    }
}

// ---------------- launch ----------------
extern "C" void kernel_launch(void* const* d_in, const int* in_sizes, int n_in,
                              void* d_out, int out_size) {
    const float* x   = (const float*)d_in[0];
    const int*   ei  = (const int*)d_in[1];
    const float* Wl0 = (const float*)d_in[2];
    const float* bl0 = (const float*)d_in[3];
    const float* Wr0 = (const float*)d_in[4];
    const float* Wl1 = (const float*)d_in[5];
    const float* bl1 = (const float*)d_in[6];
    const float* Wr1 = (const float*)d_in[7];
    const float* Wl2 = (const float*)d_in[8];
    const float* bl2 = (const float*)d_in[9];
    const float* Wr2 = (const float*)d_in[10];
    float* out = (float*)d_out;

    const int* src = ei;
    const int* dst = ei + NEDGES;

    unsigned short *xsp, *aggsp, *hsap, *hsbp;
    unsigned short *wl0p, *wr0p, *wl1p, *wr1p, *wl2p, *wr2p;
    cudaGetSymbolAddress((void**)&xsp, g_xs);
    cudaGetSymbolAddress((void**)&aggsp, g_aggs);
    cudaGetSymbolAddress((void**)&hsap, g_hsa);
    cudaGetSymbolAddress((void**)&hsbp, g_hsb);
    cudaGetSymbolAddress((void**)&wl0p, g_Wl0s);
    cudaGetSymbolAddress((void**)&wr0p, g_Wr0s);
    cudaGetSymbolAddress((void**)&wl1p, g_Wl1s);
    cudaGetSymbolAddress((void**)&wr1p, g_Wr1s);
    cudaGetSymbolAddress((void**)&wl2p, g_Wl2s);
    cudaGetSymbolAddress((void**)&wr2p, g_Wr2s);

    // ---- CSR build ----
    zero_deg_kernel<<<(NNODES + 255) / 256, 256>>>();
    hist_kernel<<<(NEDGES + 255) / 256, 256>>>(dst);
    scan_kernel<<<1, 1024>>>();
    fill_kernel<<<(NEDGES + 255) / 256, 256>>>(src, dst);

    // ---- conversions ----
    xsplit_kernel<<<(NNODES * 128 + 255) / 256, 256>>>(x, xsp);
    wsplit_kernel<<<(2 * 128 * 256 + 255) / 256, 256>>>(Wl0, wl0p, 128);
    wsplit_kernel<<<(2 * 128 * 256 + 255) / 256, 256>>>(Wr0, wr0p, 128);
    wsplit_kernel<<<(2 * 256 * 256 + 255) / 256, 256>>>(Wl1, wl1p, 256);
    wsplit_kernel<<<(2 * 256 * 256 + 255) / 256, 256>>>(Wr1, wr1p, 256);
    wsplit_kernel<<<(2 * 256 * 256 + 255) / 256, 256>>>(Wl2, wl2p, 256);
    wsplit_kernel<<<(2 * 256 * 256 + 255) / 256, 256>>>(Wr2, wr2p, 256);

    dim3 gemm_grid(2, (NNODES + 127) / 128);
    int agg_blocks = (NNODES * 32 + 255) / 256;

    // ---- layer 0: 3-term (cpp = 12), split-only output ----
    agg_split_f32_kernel<<<agg_blocks, 256>>>(x, aggsp);
    gemm_mma_kernel<<<gemm_grid, 256>>>(aggsp, xsp, 128, 12, wl0p, wr0p, bl0,
                                        nullptr, hsap, 1);

    // ---- layer 1: 2-term (cpp = 16), agg from hi plane, split-only output ----
    agg_split_hi_kernel<<<agg_blocks, 256>>>(hsap, aggsp);
    gemm_mma_kernel<<<gemm_grid, 256>>>(aggsp, hsap, 256, 16, wl1p, wr1p, bl1,
                                        nullptr, hsbp, 1);

    // ---- layer 2: 2-term, agg from hi plane, fp32 output ----
    agg_split_hi_kernel<<<agg_blocks, 256>>>(hsbp, aggsp);
    gemm_mma_kernel<<<gemm_grid, 256>>>(aggsp, hsbp, 256, 16, wl2p, wr2p, bl2,
                                        out, nullptr, 0);
}

// round 12
// speedup vs baseline: 1.1772x; 1.0437x over previous
#include <cuda_runtime.h>
#include <cuda_fp16.h>
#include <cstdint>

#define NNODES 50000
#define NEDGES 600000

// ---------------- device scratch (no allocations allowed) ----------------
__device__ int   g_deg[NNODES];
__device__ int   g_off[NNODES + 1];
__device__ int   g_cur[NNODES];
__device__ int   g_srcsorted[NEDGES];

// fp16 hi|lo split planes (stored as ushort bits)
__device__ unsigned short g_xs  [NNODES * 256];   // x split   [hi128|lo128]
__device__ unsigned short g_aggs[NNODES * 512];   // agg split [hi K |lo K]
__device__ unsigned short g_hsa [NNODES * 512];   // h0 split
__device__ unsigned short g_hsb [NNODES * 512];   // h1 split

// weight splits: W'' = [Whi ; Wlo], [2K, 256] row-major (rows = k)
__device__ unsigned short g_Wl0s[256 * 256];
__device__ unsigned short g_Wr0s[256 * 256];
__device__ unsigned short g_Wl1s[512 * 256];
__device__ unsigned short g_Wr1s[512 * 256];
__device__ unsigned short g_Wl2s[512 * 256];
__device__ unsigned short g_Wr2s[512 * 256];

// ---------------- helpers ----------------
__device__ __forceinline__ unsigned short hfbits(float f) {
    __half h = __float2half_rn(f);
    return reinterpret_cast<unsigned short&>(h);
}
__device__ __forceinline__ float hffloat(unsigned short u) {
    __half h;
    reinterpret_cast<unsigned short&>(h) = u;
    return __half2float(h);
}
__device__ __forceinline__ uint32_t smem_u32(const void* p) {
    return (uint32_t)__cvta_generic_to_shared(p);
}
__device__ __forceinline__ void cp16(uint32_t dst, const void* src, int sz) {
    asm volatile("cp.async.cg.shared.global [%0], [%1], 16, %2;\n"
                 :: "r"(dst), "l"(src), "r"(sz));
}
__device__ __forceinline__ void cp_commit() {
    asm volatile("cp.async.commit_group;\n" ::: "memory");
}

#define LDSM4(R0, R1, R2, R3, ADDR) \
    asm volatile("ldmatrix.sync.aligned.m8n8.x4.shared.b16 {%0,%1,%2,%3}, [%4];" \
                 : "=r"(R0), "=r"(R1), "=r"(R2), "=r"(R3) : "r"(ADDR))
#define LDSM4T(R0, R1, R2, R3, ADDR) \
    asm volatile("ldmatrix.sync.aligned.m8n8.x4.trans.shared.b16 {%0,%1,%2,%3}, [%4];" \
                 : "=r"(R0), "=r"(R1), "=r"(R2), "=r"(R3) : "r"(ADDR))
#define MMA16816(D, A, B) \
    asm volatile("mma.sync.aligned.m16n8k16.row.col.f32.f16.f16.f32 " \
                 "{%0,%1,%2,%3},{%4,%5,%6,%7},{%8,%9},{%0,%1,%2,%3};" \
                 : "+f"((D)[0]), "+f"((D)[1]), "+f"((D)[2]), "+f"((D)[3]) \
                 : "r"((A)[0]), "r"((A)[1]), "r"((A)[2]), "r"((A)[3]), \
                   "r"((B)[0]), "r"((B)[1]))

// ---------------- CSR build ----------------
__global__ void zero_deg_kernel() {
    int i = blockIdx.x * blockDim.x + threadIdx.x;
    if (i < NNODES) g_deg[i] = 0;
}
__global__ void hist_kernel(const int* __restrict__ dst) {
    int e = blockIdx.x * blockDim.x + threadIdx.x;
    if (e < NEDGES) atomicAdd(&g_deg[dst[e]], 1);
}
__global__ void scan_kernel() {
    __shared__ int sums[1024];
    int t = threadIdx.x;
    const int n = NNODES;
    const int chunk = (n + 1023) / 1024;
    int begin = t * chunk;
    int end = begin + chunk; if (end > n) end = n;
    int s = 0;
    for (int i = begin; i < end; ++i) s += g_deg[i];
    sums[t] = s;
    __syncthreads();
    for (int ofs = 1; ofs < 1024; ofs <<= 1) {
        int v = (t >= ofs) ? sums[t - ofs] : 0;
        __syncthreads();
        sums[t] += v;
        __syncthreads();
    }
    int prefix = (t == 0) ? 0 : sums[t - 1];
    for (int i = begin; i < end; ++i) {
        g_off[i] = prefix;
        g_cur[i] = prefix;
        prefix += g_deg[i];
    }
    if (t == 1023) g_off[n] = NEDGES;
}
__global__ void fill_kernel(const int* __restrict__ src, const int* __restrict__ dst) {
    int e = blockIdx.x * blockDim.x + threadIdx.x;
    if (e < NEDGES) {
        int d = dst[e];
        int p = atomicAdd(&g_cur[d], 1);
        g_srcsorted[p] = src[e];
    }
}

// ---------------- conversion kernels ----------------
__global__ void xsplit_kernel(const float* __restrict__ x, unsigned short* __restrict__ out) {
    int i = blockIdx.x * blockDim.x + threadIdx.x;
    if (i >= NNODES * 128) return;
    int r = i >> 7, c = i & 127;
    float f = x[i];
    unsigned short hb = hfbits(f);
    out[r * 256 + c] = hb;
    out[r * 256 + 128 + c] = hfbits(f - hffloat(hb));
}
// W [K,256] row-major -> out [2K, 256]: rows [0,K)=hi, [K,2K)=lo
__global__ void wsplit_kernel(const float* __restrict__ W, unsigned short* __restrict__ out, int K) {
    int i = blockIdx.x * blockDim.x + threadIdx.x;
    int total = 2 * K * 256;
    if (i >= total) return;
    int r = i >> 8, c = i & 255;
    if (r < K) {
        out[i] = hfbits(W[r * 256 + c]);
    } else {
        float f = W[(r - K) * 256 + c];
        unsigned short hb = hfbits(f);
        out[i] = hfbits(f - hffloat(hb));
    }
}

// ---------------- aggregation ----------------
__device__ __forceinline__ void split_store4(float4 v, unsigned short* hip, unsigned short* lop) {
    unsigned short h0 = hfbits(v.x), h1 = hfbits(v.y), h2 = hfbits(v.z), h3 = hfbits(v.w);
    uint2 hi = make_uint2((uint32_t)h0 | ((uint32_t)h1 << 16),
                          (uint32_t)h2 | ((uint32_t)h3 << 16));
    *(uint2*)hip = hi;
    unsigned short l0 = hfbits(v.x - hffloat(h0));
    unsigned short l1 = hfbits(v.y - hffloat(h1));
    unsigned short l2 = hfbits(v.z - hffloat(h2));
    unsigned short l3 = hfbits(v.w - hffloat(h3));
    uint2 lo = make_uint2((uint32_t)l0 | ((uint32_t)l1 << 16),
                          (uint32_t)l2 | ((uint32_t)l3 << 16));
    *(uint2*)lop = lo;
}

// layer 0: gather fp16 hi plane of x split (D=128, row stride 256)
__global__ void agg_split_hi128_kernel(const unsigned short* __restrict__ hs,
                                       unsigned short* __restrict__ outs) {
    int warp = (blockIdx.x * blockDim.x + threadIdx.x) >> 5;
    if (warp >= NNODES) return;
    int lane = threadIdx.x & 31;
    int s = g_off[warp];
    int e = g_off[warp + 1];
    int cnt = e - s;
    float inv = 1.0f / (float)(cnt > 0 ? cnt : 1);
    int c0 = lane * 4;
    unsigned short* orow = outs + (size_t)warp * 256;

    float4 acc = make_float4(0.f, 0.f, 0.f, 0.f);
    for (int i = s; i < e; ++i) {
        int src = g_srcsorted[i];
        uint2 u = *(const uint2*)&hs[(size_t)src * 256 + c0];
        __half2 p;
        float2 f;
        reinterpret_cast<uint32_t&>(p) = u.x; f = __half22float2(p);
        acc.x += f.x; acc.y += f.y;
        reinterpret_cast<uint32_t&>(p) = u.y; f = __half22float2(p);
        acc.z += f.x; acc.w += f.y;
    }
    acc.x *= inv; acc.y *= inv; acc.z *= inv; acc.w *= inv;
    split_store4(acc, orow + c0, orow + 128 + c0);
}

// layers 1/2: gather fp16 hi plane of split buffer (D=256, row stride 512)
__global__ void agg_split_hi_kernel(const unsigned short* __restrict__ hs,
                                    unsigned short* __restrict__ outs) {
    int warp = (blockIdx.x * blockDim.x + threadIdx.x) >> 5;
    if (warp >= NNODES) return;
    int lane = threadIdx.x & 31;
    int s = g_off[warp];
    int e = g_off[warp + 1];
    int cnt = e - s;
    float inv = 1.0f / (float)(cnt > 0 ? cnt : 1);
    int c0 = lane * 4;
    unsigned short* orow = outs + (size_t)warp * 512;

    float4 a0 = make_float4(0.f, 0.f, 0.f, 0.f);
    float4 a1 = make_float4(0.f, 0.f, 0.f, 0.f);
    for (int i = s; i < e; ++i) {
        int src = g_srcsorted[i];
        const unsigned short* row = hs + (size_t)src * 512;
        uint2 u0 = *(const uint2*)&row[c0];
        uint2 u1 = *(const uint2*)&row[c0 + 128];
        __half2 p;
        float2 f;
        reinterpret_cast<uint32_t&>(p) = u0.x; f = __half22float2(p);
        a0.x += f.x; a0.y += f.y;
        reinterpret_cast<uint32_t&>(p) = u0.y; f = __half22float2(p);
        a0.z += f.x; a0.w += f.y;
        reinterpret_cast<uint32_t&>(p) = u1.x; f = __half22float2(p);
        a1.x += f.x; a1.y += f.y;
        reinterpret_cast<uint32_t&>(p) = u1.y; f = __half22float2(p);
        a1.z += f.x; a1.w += f.y;
    }
    a0.x *= inv; a0.y *= inv; a0.z *= inv; a0.w *= inv;
    a1.x *= inv; a1.y *= inv; a1.z *= inv; a1.w *= inv;
    split_store4(a0, orow + c0, orow + 256 + c0);
    split_store4(a1, orow + 128 + c0, orow + 256 + 128 + c0);
}

// ---------------- fused fp16 MMA GEMM (two passes), split-term schedule ----------------
// A planes: [M, 2Kp] fp16 (cols [0,Kp)=hi, [Kp,2Kp)=lo).
// B'' = [2Kp, 256] fp16 (rows [0,Kp)=hi, [Kp,2Kp)=lo).
// Within a pass, chunks kb = 0..cpp*32:
//   kb in [0,Kp):     Ahi*Bhi   kb in [Kp,2Kp): Alo*Bhi   kb in [2Kp,3Kp): Ahi*Blo
// cpp = 2*Kp/32 -> 2-term; cpp = 3*Kp/32 -> 3-term. nchunks = 2*cpp (pass0=A0/B0, pass1=A1/B1).
__global__ void __launch_bounds__(256, 2)
gemm_mma_kernel(const unsigned short* __restrict__ A0,
                const unsigned short* __restrict__ A1,
                int Kp, int cpp,
                const unsigned short* __restrict__ B0,
                const unsigned short* __restrict__ B1,
                const float* __restrict__ bias,
                float* __restrict__ Cout,
                unsigned short* __restrict__ Csplit,
                int relu) {
    constexpr int AP = 40;    // As row pad (fp16 elems)
    constexpr int BP = 136;   // Bs row pad
    __shared__ unsigned short As[2][128 * AP];
    __shared__ unsigned short Bs[2][32 * BP];

    const int tid = threadIdx.x;
    const int warp = tid >> 5;
    const int lane = tid & 31;
    const int warp_m = warp & 3;   // 4 warps of 32 rows
    const int warp_n = warp >> 2;  // 2 warps of 64 cols
    const int m0 = blockIdx.y * 128;
    const int n0 = blockIdx.x * 128;

    const int astride = 2 * Kp;
    const int nchunks = 2 * cpp;

    float acc[2][8][4];
#pragma unroll
    for (int mt = 0; mt < 2; ++mt)
#pragma unroll
        for (int nt = 0; nt < 8; ++nt)
#pragma unroll
            for (int q = 0; q < 4; ++q) acc[mt][nt][q] = 0.f;

    uint32_t as_base[2] = { smem_u32(&As[0][0]), smem_u32(&As[1][0]) };
    uint32_t bs_base[2] = { smem_u32(&Bs[0][0]), smem_u32(&Bs[1][0]) };

    // ---- tile loader ----
    auto load_tile = [&](int c, int buf) {
        int pass = (c >= cpp) ? 1 : 0;
        int kb = (c - pass * cpp) << 5;
        int acol = (kb < 2 * Kp) ? kb : kb - 2 * Kp;
        int brow = (kb < Kp) ? kb : kb - Kp;
        const unsigned short* A = pass ? A1 : A0;
        const unsigned short* B = pass ? B1 : B0;
        // A tile: 128 rows x 32 cols
        {
            int r = tid >> 2;
            int kc = (tid & 3) << 3;
#pragma unroll
            for (int i = 0; i < 2; ++i) {
                int row = r + i * 64;
                int grow = m0 + row;
                int ok = grow < NNODES;
                const unsigned short* src = A + (size_t)(ok ? grow : 0) * astride + acol + kc;
                cp16(as_base[buf] + (row * AP + kc) * 2, src, ok ? 16 : 0);
            }
        }
        // B tile: 32 rows x 128 cols
        {
            int r = tid >> 4;
            int col = (tid & 15) << 3;
#pragma unroll
            for (int i = 0; i < 2; ++i) {
                int row = r + i * 16;
                const unsigned short* src = B + (size_t)(brow + row) * 256 + n0 + col;
                cp16(bs_base[buf] + (row * BP + col) * 2, src, 16);
            }
        }
        cp_commit();
    };

    load_tile(0, 0);

    for (int c = 0; c < nchunks; ++c) {
        if (c + 1 < nchunks) {
            load_tile(c + 1, (c + 1) & 1);
            asm volatile("cp.async.wait_group 1;\n" ::: "memory");
        } else {
            asm volatile("cp.async.wait_group 0;\n" ::: "memory");
        }
        __syncthreads();

        int buf = c & 1;
        uint32_t ab = as_base[buf];
        uint32_t bb = bs_base[buf];
#pragma unroll
        for (int k16 = 0; k16 < 32; k16 += 16) {
            uint32_t a[2][4];
#pragma unroll
            for (int mt = 0; mt < 2; ++mt) {
                int mrow = warp_m * 32 + mt * 16 + (lane & 15);
                int kc = k16 + ((lane >> 4) << 3);
                LDSM4(a[mt][0], a[mt][1], a[mt][2], a[mt][3], ab + (mrow * AP + kc) * 2);
            }
            uint32_t b[8][2];
#pragma unroll
            for (int p = 0; p < 4; ++p) {
                int brow2 = k16 + (lane & 15);
                int bcol = warp_n * 64 + p * 16 + ((lane >> 4) << 3);
                LDSM4T(b[2 * p][0], b[2 * p][1], b[2 * p + 1][0], b[2 * p + 1][1],
                       bb + (brow2 * BP + bcol) * 2);
            }
#pragma unroll
            for (int mt = 0; mt < 2; ++mt)
#pragma unroll
                for (int nt = 0; nt < 8; ++nt)
                    MMA16816(acc[mt][nt], a[mt], b[nt]);
        }
        __syncthreads();
    }

    // ---- epilogue ----
    int g = lane >> 2;
    int tg = lane & 3;
#pragma unroll
    for (int mt = 0; mt < 2; ++mt) {
#pragma unroll
        for (int nt = 0; nt < 8; ++nt) {
            int col = n0 + warp_n * 64 + nt * 8 + tg * 2;
            float b0 = bias[col], b1 = bias[col + 1];
            int r0 = m0 + warp_m * 32 + mt * 16 + g;
            int r1 = r0 + 8;
            float v0 = acc[mt][nt][0] + b0;
            float v1 = acc[mt][nt][1] + b1;
            float v2 = acc[mt][nt][2] + b0;
            float v3 = acc[mt][nt][3] + b1;
            if (relu) {
                v0 = v0 > 0.f ? v0 : 0.f;
                v1 = v1 > 0.f ? v1 : 0.f;
                v2 = v2 > 0.f ? v2 : 0.f;
                v3 = v3 > 0.f ? v3 : 0.f;
            }
            if (r0 < NNODES) {
                if (Cout) *(float2*)&Cout[(size_t)r0 * 256 + col] = make_float2(v0, v1);
                if (Csplit) {
                    unsigned short h0 = hfbits(v0), h1 = hfbits(v1);
                    *(uint32_t*)&Csplit[(size_t)r0 * 512 + col] =
                        (uint32_t)h0 | ((uint32_t)h1 << 16);
                    unsigned short l0 = hfbits(v0 - hffloat(h0));
                    unsigned short l1 = hfbits(v1 - hffloat(h1));
                    *(uint32_t*)&Csplit[(size_t)r0 * 512 + 256 + col] =
                        (uint32_t)l0 | ((uint32_t)l1 << 16);
                }
            }
            if (r1 < NNODES) {
                if (Cout) *(float2*)&Cout[(size_t)r1 * 256 + col] = make_float2(v2, v3);
                if (Csplit) {
                    unsigned short h2 = hfbits(v2), h3 = hfbits(v3);
                    *(uint32_t*)&Csplit[(size_t)r1 * 512 + col] =
                        (uint32_t)h2 | ((uint32_t)h3 << 16);
                    unsigned short l2 = hfbits(v2 - hffloat(h2));
                    unsigned short l3 = hfbits(v3 - hffloat(h3));
                    *(uint32_t*)&Csplit[(size_t)r1 * 512 + 256 + col] =
                        (uint32_t)l2 | ((uint32_t)l3 << 16);
                }
            }
        }
    }
}

// ---------------- launch ----------------
extern "C" void kernel_launch(void* const* d_in, const int* in_sizes, int n_in,
                              void* d_out, int out_size) {
    const float* x   = (const float*)d_in[0];
    const int*   ei  = (const int*)d_in[1];
    const float* Wl0 = (const float*)d_in[2];
    const float* bl0 = (const float*)d_in[3];
    const float* Wr0 = (const float*)d_in[4];
    const float* Wl1 = (const float*)d_in[5];
    const float* bl1 = (const float*)d_in[6];
    const float* Wr1 = (const float*)d_in[7];
    const float* Wl2 = (const float*)d_in[8];
    const float* bl2 = (const float*)d_in[9];
    const float* Wr2 = (const float*)d_in[10];
    float* out = (float*)d_out;

    const int* src = ei;
    const int* dst = ei + NEDGES;

    unsigned short *xsp, *aggsp, *hsap, *hsbp;
    unsigned short *wl0p, *wr0p, *wl1p, *wr1p, *wl2p, *wr2p;
    cudaGetSymbolAddress((void**)&xsp, g_xs);
    cudaGetSymbolAddress((void**)&aggsp, g_aggs);
    cudaGetSymbolAddress((void**)&hsap, g_hsa);
    cudaGetSymbolAddress((void**)&hsbp, g_hsb);
    cudaGetSymbolAddress((void**)&wl0p, g_Wl0s);
    cudaGetSymbolAddress((void**)&wr0p, g_Wr0s);
    cudaGetSymbolAddress((void**)&wl1p, g_Wl1s);
    cudaGetSymbolAddress((void**)&wr1p, g_Wr1s);
    cudaGetSymbolAddress((void**)&wl2p, g_Wl2s);
    cudaGetSymbolAddress((void**)&wr2p, g_Wr2s);

    // ---- CSR build ----
    zero_deg_kernel<<<(NNODES + 255) / 256, 256>>>();
    hist_kernel<<<(NEDGES + 255) / 256, 256>>>(dst);
    scan_kernel<<<1, 1024>>>();
    fill_kernel<<<(NEDGES + 255) / 256, 256>>>(src, dst);

    // ---- conversions ----
    xsplit_kernel<<<(NNODES * 128 + 255) / 256, 256>>>(x, xsp);
    wsplit_kernel<<<(2 * 128 * 256 + 255) / 256, 256>>>(Wl0, wl0p, 128);
    wsplit_kernel<<<(2 * 128 * 256 + 255) / 256, 256>>>(Wr0, wr0p, 128);
    wsplit_kernel<<<(2 * 256 * 256 + 255) / 256, 256>>>(Wl1, wl1p, 256);
    wsplit_kernel<<<(2 * 256 * 256 + 255) / 256, 256>>>(Wr1, wr1p, 256);
    wsplit_kernel<<<(2 * 256 * 256 + 255) / 256, 256>>>(Wl2, wl2p, 256);
    wsplit_kernel<<<(2 * 256 * 256 + 255) / 256, 256>>>(Wr2, wr2p, 256);

    dim3 gemm_grid(2, (NNODES + 127) / 128);
    int agg_blocks = (NNODES * 32 + 255) / 256;

    // ---- layer 0: 2-term (cpp = 2*128/32 = 8), agg from x hi plane, split-only output ----
    agg_split_hi128_kernel<<<agg_blocks, 256>>>(xsp, aggsp);
    gemm_mma_kernel<<<gemm_grid, 256>>>(aggsp, xsp, 128, 8, wl0p, wr0p, bl0,
                                        nullptr, hsap, 1);

    // ---- layer 1: 2-term (cpp = 16), agg from hi plane, split-only output ----
    agg_split_hi_kernel<<<agg_blocks, 256>>>(hsap, aggsp);
    gemm_mma_kernel<<<gemm_grid, 256>>>(aggsp, hsap, 256, 16, wl1p, wr1p, bl1,
                                        nullptr, hsbp, 1);

    // ---- layer 2: 2-term, agg from hi plane, fp32 output ----
    agg_split_hi_kernel<<<agg_blocks, 256>>>(hsbp, aggsp);
    gemm_mma_kernel<<<gemm_grid, 256>>>(aggsp, hsbp, 256, 16, wl2p, wr2p, bl2,
                                        out, nullptr, 0);
}

// round 14
// speedup vs baseline: 1.5232x; 1.2939x over previous
#include <cuda_runtime.h>
#include <cuda_fp16.h>
#include <cstdint>

#define NNODES 50000
#define NEDGES 600000

// ---------------- device scratch (no allocations allowed) ----------------
__device__ int   g_deg[NNODES];
__device__ int   g_off[NNODES + 1];
__device__ int   g_cur[NNODES];
__device__ int   g_srcsorted[NEDGES];

// fp16 hi|lo split planes (stored as ushort bits)
__device__ unsigned short g_xs  [NNODES * 256];   // x split   [hi128|lo128]
__device__ unsigned short g_aggs[NNODES * 512];   // agg split [hi K |lo K]
__device__ unsigned short g_hsa [NNODES * 512];   // h0 (hi plane used only)
__device__ unsigned short g_hsb [NNODES * 512];   // h1 (hi plane used only)

// weight splits: W'' = [Whi ; Wlo], [2K, 256] row-major (rows = k)
__device__ unsigned short g_Wl0s[256 * 256];
__device__ unsigned short g_Wr0s[256 * 256];
__device__ unsigned short g_Wl1s[512 * 256];
__device__ unsigned short g_Wr1s[512 * 256];
__device__ unsigned short g_Wl2s[512 * 256];
__device__ unsigned short g_Wr2s[512 * 256];

// ---------------- helpers ----------------
__device__ __forceinline__ unsigned short hfbits(float f) {
    __half h = __float2half_rn(f);
    return reinterpret_cast<unsigned short&>(h);
}
__device__ __forceinline__ float hffloat(unsigned short u) {
    __half h;
    reinterpret_cast<unsigned short&>(h) = u;
    return __half2float(h);
}
__device__ __forceinline__ uint32_t smem_u32(const void* p) {
    return (uint32_t)__cvta_generic_to_shared(p);
}
__device__ __forceinline__ void cp16(uint32_t dst, const void* src, int sz) {
    asm volatile("cp.async.cg.shared.global [%0], [%1], 16, %2;\n"
                 :: "r"(dst), "l"(src), "r"(sz));
}
__device__ __forceinline__ void cp_commit() {
    asm volatile("cp.async.commit_group;\n" ::: "memory");
}

#define LDSM4(R0, R1, R2, R3, ADDR) \
    asm volatile("ldmatrix.sync.aligned.m8n8.x4.shared.b16 {%0,%1,%2,%3}, [%4];" \
                 : "=r"(R0), "=r"(R1), "=r"(R2), "=r"(R3) : "r"(ADDR))
#define LDSM4T(R0, R1, R2, R3, ADDR) \
    asm volatile("ldmatrix.sync.aligned.m8n8.x4.trans.shared.b16 {%0,%1,%2,%3}, [%4];" \
                 : "=r"(R0), "=r"(R1), "=r"(R2), "=r"(R3) : "r"(ADDR))
#define MMA16816(D, A, B) \
    asm volatile("mma.sync.aligned.m16n8k16.row.col.f32.f16.f16.f32 " \
                 "{%0,%1,%2,%3},{%4,%5,%6,%7},{%8,%9},{%0,%1,%2,%3};" \
                 : "+f"((D)[0]), "+f"((D)[1]), "+f"((D)[2]), "+f"((D)[3]) \
                 : "r"((A)[0]), "r"((A)[1]), "r"((A)[2]), "r"((A)[3]), \
                   "r"((B)[0]), "r"((B)[1]))

// ---------------- CSR build ----------------
__global__ void zero_deg_kernel() {
    int i = blockIdx.x * blockDim.x + threadIdx.x;
    if (i < NNODES) g_deg[i] = 0;
}
__global__ void hist_kernel(const int* __restrict__ dst) {
    int e = blockIdx.x * blockDim.x + threadIdx.x;
    if (e < NEDGES) atomicAdd(&g_deg[dst[e]], 1);
}
__global__ void scan_kernel() {
    __shared__ int sums[1024];
    int t = threadIdx.x;
    const int n = NNODES;
    const int chunk = (n + 1023) / 1024;
    int begin = t * chunk;
    int end = begin + chunk; if (end > n) end = n;
    int s = 0;
    for (int i = begin; i < end; ++i) s += g_deg[i];
    sums[t] = s;
    __syncthreads();
    for (int ofs = 1; ofs < 1024; ofs <<= 1) {
        int v = (t >= ofs) ? sums[t - ofs] : 0;
        __syncthreads();
        sums[t] += v;
        __syncthreads();
    }
    int prefix = (t == 0) ? 0 : sums[t - 1];
    for (int i = begin; i < end; ++i) {
        g_off[i] = prefix;
        g_cur[i] = prefix;
        prefix += g_deg[i];
    }
    if (t == 1023) g_off[n] = NEDGES;
}
__global__ void fill_kernel(const int* __restrict__ src, const int* __restrict__ dst) {
    int e = blockIdx.x * blockDim.x + threadIdx.x;
    if (e < NEDGES) {
        int d = dst[e];
        int p = atomicAdd(&g_cur[d], 1);
        g_srcsorted[p] = src[e];
    }
}

// ---------------- conversion kernels ----------------
__global__ void xsplit_kernel(const float* __restrict__ x, unsigned short* __restrict__ out) {
    int i = blockIdx.x * blockDim.x + threadIdx.x;
    if (i >= NNODES * 128) return;
    int r = i >> 7, c = i & 127;
    float f = x[i];
    unsigned short hb = hfbits(f);
    out[r * 256 + c] = hb;
    out[r * 256 + 128 + c] = hfbits(f - hffloat(hb));
}
// W [K,256] row-major -> out [2K, 256]: rows [0,K)=hi, [K,2K)=lo
__global__ void wsplit_kernel(const float* __restrict__ W, unsigned short* __restrict__ out, int K) {
    int i = blockIdx.x * blockDim.x + threadIdx.x;
    int total = 2 * K * 256;
    if (i >= total) return;
    int r = i >> 8, c = i & 255;
    if (r < K) {
        out[i] = hfbits(W[r * 256 + c]);
    } else {
        float f = W[(r - K) * 256 + c];
        unsigned short hb = hfbits(f);
        out[i] = hfbits(f - hffloat(hb));
    }
}

// ---------------- aggregation ----------------
__device__ __forceinline__ void split_store4(float4 v, unsigned short* hip, unsigned short* lop) {
    unsigned short h0 = hfbits(v.x), h1 = hfbits(v.y), h2 = hfbits(v.z), h3 = hfbits(v.w);
    uint2 hi = make_uint2((uint32_t)h0 | ((uint32_t)h1 << 16),
                          (uint32_t)h2 | ((uint32_t)h3 << 16));
    *(uint2*)hip = hi;
    unsigned short l0 = hfbits(v.x - hffloat(h0));
    unsigned short l1 = hfbits(v.y - hffloat(h1));
    unsigned short l2 = hfbits(v.z - hffloat(h2));
    unsigned short l3 = hfbits(v.w - hffloat(h3));
    uint2 lo = make_uint2((uint32_t)l0 | ((uint32_t)l1 << 16),
                          (uint32_t)l2 | ((uint32_t)l3 << 16));
    *(uint2*)lop = lo;
}
__device__ __forceinline__ void hi_store4(float4 v, unsigned short* hip) {
    unsigned short h0 = hfbits(v.x), h1 = hfbits(v.y), h2 = hfbits(v.z), h3 = hfbits(v.w);
    uint2 hi = make_uint2((uint32_t)h0 | ((uint32_t)h1 << 16),
                          (uint32_t)h2 | ((uint32_t)h3 << 16));
    *(uint2*)hip = hi;
}

// layer 0: gather fp16 hi plane of x split (D=128, row stride 256); full split out (L0 GEMM is 2-term)
__global__ void agg_split_hi128_kernel(const unsigned short* __restrict__ hs,
                                       unsigned short* __restrict__ outs) {
    int warp = (blockIdx.x * blockDim.x + threadIdx.x) >> 5;
    if (warp >= NNODES) return;
    int lane = threadIdx.x & 31;
    int s = g_off[warp];
    int e = g_off[warp + 1];
    int cnt = e - s;
    float inv = 1.0f / (float)(cnt > 0 ? cnt : 1);
    int c0 = lane * 4;
    unsigned short* orow = outs + (size_t)warp * 256;

    float4 acc = make_float4(0.f, 0.f, 0.f, 0.f);
    for (int i = s; i < e; ++i) {
        int src = g_srcsorted[i];
        uint2 u = *(const uint2*)&hs[(size_t)src * 256 + c0];
        __half2 p;
        float2 f;
        reinterpret_cast<uint32_t&>(p) = u.x; f = __half22float2(p);
        acc.x += f.x; acc.y += f.y;
        reinterpret_cast<uint32_t&>(p) = u.y; f = __half22float2(p);
        acc.z += f.x; acc.w += f.y;
    }
    acc.x *= inv; acc.y *= inv; acc.z *= inv; acc.w *= inv;
    split_store4(acc, orow + c0, orow + 128 + c0);
}

// layers 1/2: gather fp16 hi plane (D=256, row stride 512); hi-only out (1-term GEMM)
__global__ void agg_split_hi_kernel(const unsigned short* __restrict__ hs,
                                    unsigned short* __restrict__ outs) {
    int warp = (blockIdx.x * blockDim.x + threadIdx.x) >> 5;
    if (warp >= NNODES) return;
    int lane = threadIdx.x & 31;
    int s = g_off[warp];
    int e = g_off[warp + 1];
    int cnt = e - s;
    float inv = 1.0f / (float)(cnt > 0 ? cnt : 1);
    int c0 = lane * 4;
    unsigned short* orow = outs + (size_t)warp * 512;

    float4 a0 = make_float4(0.f, 0.f, 0.f, 0.f);
    float4 a1 = make_float4(0.f, 0.f, 0.f, 0.f);
    for (int i = s; i < e; ++i) {
        int src = g_srcsorted[i];
        const unsigned short* row = hs + (size_t)src * 512;
        uint2 u0 = *(const uint2*)&row[c0];
        uint2 u1 = *(const uint2*)&row[c0 + 128];
        __half2 p;
        float2 f;
        reinterpret_cast<uint32_t&>(p) = u0.x; f = __half22float2(p);
        a0.x += f.x; a0.y += f.y;
        reinterpret_cast<uint32_t&>(p) = u0.y; f = __half22float2(p);
        a0.z += f.x; a0.w += f.y;
        reinterpret_cast<uint32_t&>(p) = u1.x; f = __half22float2(p);
        a1.x += f.x; a1.y += f.y;
        reinterpret_cast<uint32_t&>(p) = u1.y; f = __half22float2(p);
        a1.z += f.x; a1.w += f.y;
    }
    a0.x *= inv; a0.y *= inv; a0.z *= inv; a0.w *= inv;
    a1.x *= inv; a1.y *= inv; a1.z *= inv; a1.w *= inv;
    hi_store4(a0, orow + c0);
    hi_store4(a1, orow + 128 + c0);
}

// ---------------- fused fp16 MMA GEMM (two passes), split-term schedule ----------------
// A planes: [M, 2Kp] fp16 (cols [0,Kp)=hi, [Kp,2Kp)=lo).
// B'' = [2Kp, 256] fp16 (rows [0,Kp)=hi, [Kp,2Kp)=lo).
// Within a pass, chunks kb = 0..cpp*32:
//   kb in [0,Kp):     Ahi*Bhi   kb in [Kp,2Kp): Alo*Bhi   kb in [2Kp,3Kp): Ahi*Blo
// cpp = Kp/32 -> 1-term; 2*Kp/32 -> 2-term; 3*Kp/32 -> 3-term.
// Epilogue: Csplit (if set) stores HI PLANE ONLY (consumers are 1-term GEMMs + hi-plane aggs).
__global__ void __launch_bounds__(256, 2)
gemm_mma_kernel(const unsigned short* __restrict__ A0,
                const unsigned short* __restrict__ A1,
                int Kp, int cpp,
                const unsigned short* __restrict__ B0,
                const unsigned short* __restrict__ B1,
                const float* __restrict__ bias,
                float* __restrict__ Cout,
                unsigned short* __restrict__ Csplit,
                int relu) {
    constexpr int AP = 40;    // As row pad (fp16 elems)
    constexpr int BP = 136;   // Bs row pad
    __shared__ unsigned short As[2][128 * AP];
    __shared__ unsigned short Bs[2][32 * BP];

    const int tid = threadIdx.x;
    const int warp = tid >> 5;
    const int lane = tid & 31;
    const int warp_m = warp & 3;   // 4 warps of 32 rows
    const int warp_n = warp >> 2;  // 2 warps of 64 cols
    const int m0 = blockIdx.y * 128;
    const int n0 = blockIdx.x * 128;

    const int astride = 2 * Kp;
    const int nchunks = 2 * cpp;

    float acc[2][8][4];
#pragma unroll
    for (int mt = 0; mt < 2; ++mt)
#pragma unroll
        for (int nt = 0; nt < 8; ++nt)
#pragma unroll
            for (int q = 0; q < 4; ++q) acc[mt][nt][q] = 0.f;

    uint32_t as_base[2] = { smem_u32(&As[0][0]), smem_u32(&As[1][0]) };
    uint32_t bs_base[2] = { smem_u32(&Bs[0][0]), smem_u32(&Bs[1][0]) };

    // ---- tile loader ----
    auto load_tile = [&](int c, int buf) {
        int pass = (c >= cpp) ? 1 : 0;
        int kb = (c - pass * cpp) << 5;
        int acol = (kb < 2 * Kp) ? kb : kb - 2 * Kp;
        int brow = (kb < Kp) ? kb : kb - Kp;
        const unsigned short* A = pass ? A1 : A0;
        const unsigned short* B = pass ? B1 : B0;
        // A tile: 128 rows x 32 cols
        {
            int r = tid >> 2;
            int kc = (tid & 3) << 3;
#pragma unroll
            for (int i = 0; i < 2; ++i) {
                int row = r + i * 64;
                int grow = m0 + row;
                int ok = grow < NNODES;
                const unsigned short* src = A + (size_t)(ok ? grow : 0) * astride + acol + kc;
                cp16(as_base[buf] + (row * AP + kc) * 2, src, ok ? 16 : 0);
            }
        }
        // B tile: 32 rows x 128 cols
        {
            int r = tid >> 4;
            int col = (tid & 15) << 3;
#pragma unroll
            for (int i = 0; i < 2; ++i) {
                int row = r + i * 16;
                const unsigned short* src = B + (size_t)(brow + row) * 256 + n0 + col;
                cp16(bs_base[buf] + (row * BP + col) * 2, src, 16);
            }
        }
        cp_commit();
    };

    load_tile(0, 0);

    for (int c = 0; c < nchunks; ++c) {
        if (c + 1 < nchunks) {
            load_tile(c + 1, (c + 1) & 1);
            asm volatile("cp.async.wait_group 1;\n" ::: "memory");
        } else {
            asm volatile("cp.async.wait_group 0;\n" ::: "memory");
        }
        __syncthreads();

        int buf = c & 1;
        uint32_t ab = as_base[buf];
        uint32_t bb = bs_base[buf];
#pragma unroll
        for (int k16 = 0; k16 < 32; k16 += 16) {
            uint32_t a[2][4];
#pragma unroll
            for (int mt = 0; mt < 2; ++mt) {
                int mrow = warp_m * 32 + mt * 16 + (lane & 15);
                int kc = k16 + ((lane >> 4) << 3);
                LDSM4(a[mt][0], a[mt][1], a[mt][2], a[mt][3], ab + (mrow * AP + kc) * 2);
            }
            uint32_t b[8][2];
#pragma unroll
            for (int p = 0; p < 4; ++p) {
                int brow2 = k16 + (lane & 15);
                int bcol = warp_n * 64 + p * 16 + ((lane >> 4) << 3);
                LDSM4T(b[2 * p][0], b[2 * p][1], b[2 * p + 1][0], b[2 * p + 1][1],
                       bb + (brow2 * BP + bcol) * 2);
            }
#pragma unroll
            for (int mt = 0; mt < 2; ++mt)
#pragma unroll
                for (int nt = 0; nt < 8; ++nt)
                    MMA16816(acc[mt][nt], a[mt], b[nt]);
        }
        __syncthreads();
    }

    // ---- epilogue (Csplit: hi plane only) ----
    int g = lane >> 2;
    int tg = lane & 3;
#pragma unroll
    for (int mt = 0; mt < 2; ++mt) {
#pragma unroll
        for (int nt = 0; nt < 8; ++nt) {
            int col = n0 + warp_n * 64 + nt * 8 + tg * 2;
            float b0 = bias[col], b1 = bias[col + 1];
            int r0 = m0 + warp_m * 32 + mt * 16 + g;
            int r1 = r0 + 8;
            float v0 = acc[mt][nt][0] + b0;
            float v1 = acc[mt][nt][1] + b1;
            float v2 = acc[mt][nt][2] + b0;
            float v3 = acc[mt][nt][3] + b1;
            if (relu) {
                v0 = v0 > 0.f ? v0 : 0.f;
                v1 = v1 > 0.f ? v1 : 0.f;
                v2 = v2 > 0.f ? v2 : 0.f;
                v3 = v3 > 0.f ? v3 : 0.f;
            }
            if (r0 < NNODES) {
                if (Cout) *(float2*)&Cout[(size_t)r0 * 256 + col] = make_float2(v0, v1);
                if (Csplit) {
                    unsigned short h0 = hfbits(v0), h1 = hfbits(v1);
                    *(uint32_t*)&Csplit[(size_t)r0 * 512 + col] =
                        (uint32_t)h0 | ((uint32_t)h1 << 16);
                }
            }
            if (r1 < NNODES) {
                if (Cout) *(float2*)&Cout[(size_t)r1 * 256 + col] = make_float2(v2, v3);
                if (Csplit) {
                    unsigned short h2 = hfbits(v2), h3 = hfbits(v3);
                    *(uint32_t*)&Csplit[(size_t)r1 * 512 + col] =
                        (uint32_t)h2 | ((uint32_t)h3 << 16);
                }
            }
        }
    }
}

// ---------------- launch ----------------
extern "C" void kernel_launch(void* const* d_in, const int* in_sizes, int n_in,
                              void* d_out, int out_size) {
    const float* x   = (const float*)d_in[0];
    const int*   ei  = (const int*)d_in[1];
    const float* Wl0 = (const float*)d_in[2];
    const float* bl0 = (const float*)d_in[3];
    const float* Wr0 = (const float*)d_in[4];
    const float* Wl1 = (const float*)d_in[5];
    const float* bl1 = (const float*)d_in[6];
    const float* Wr1 = (const float*)d_in[7];
    const float* Wl2 = (const float*)d_in[8];
    const float* bl2 = (const float*)d_in[9];
    const float* Wr2 = (const float*)d_in[10];
    float* out = (float*)d_out;

    const int* src = ei;
    const int* dst = ei + NEDGES;

    unsigned short *xsp, *aggsp, *hsap, *hsbp;
    unsigned short *wl0p, *wr0p, *wl1p, *wr1p, *wl2p, *wr2p;
    cudaGetSymbolAddress((void**)&xsp, g_xs);
    cudaGetSymbolAddress((void**)&aggsp, g_aggs);
    cudaGetSymbolAddress((void**)&hsap, g_hsa);
    cudaGetSymbolAddress((void**)&hsbp, g_hsb);
    cudaGetSymbolAddress((void**)&wl0p, g_Wl0s);
    cudaGetSymbolAddress((void**)&wr0p, g_Wr0s);
    cudaGetSymbolAddress((void**)&wl1p, g_Wl1s);
    cudaGetSymbolAddress((void**)&wr1p, g_Wr1s);
    cudaGetSymbolAddress((void**)&wl2p, g_Wl2s);
    cudaGetSymbolAddress((void**)&wr2p, g_Wr2s);

    // ---- CSR build ----
    zero_deg_kernel<<<(NNODES + 255) / 256, 256>>>();
    hist_kernel<<<(NEDGES + 255) / 256, 256>>>(dst);
    scan_kernel<<<1, 1024>>>();
    fill_kernel<<<(NEDGES + 255) / 256, 256>>>(src, dst);

    // ---- conversions ----
    xsplit_kernel<<<(NNODES * 128 + 255) / 256, 256>>>(x, xsp);
    wsplit_kernel<<<(2 * 128 * 256 + 255) / 256, 256>>>(Wl0, wl0p, 128);
    wsplit_kernel<<<(2 * 128 * 256 + 255) / 256, 256>>>(Wr0, wr0p, 128);
    wsplit_kernel<<<(2 * 256 * 256 + 255) / 256, 256>>>(Wl1, wl1p, 256);
    wsplit_kernel<<<(2 * 256 * 256 + 255) / 256, 256>>>(Wr1, wr1p, 256);
    wsplit_kernel<<<(2 * 256 * 256 + 255) / 256, 256>>>(Wl2, wl2p, 256);
    wsplit_kernel<<<(2 * 256 * 256 + 255) / 256, 256>>>(Wr2, wr2p, 256);

    dim3 gemm_grid(2, (NNODES + 127) / 128);
    int agg_blocks = (NNODES * 32 + 255) / 256;

    // ---- layer 0: 2-term (cpp = 8), agg from x hi plane, split(hi)-only output ----
    agg_split_hi128_kernel<<<agg_blocks, 256>>>(xsp, aggsp);
    gemm_mma_kernel<<<gemm_grid, 256>>>(aggsp, xsp, 128, 8, wl0p, wr0p, bl0,
                                        nullptr, hsap, 1);

    // ---- layer 1: 1-term (cpp = 256/32 = 8), agg hi-only, split(hi)-only output ----
    agg_split_hi_kernel<<<agg_blocks, 256>>>(hsap, aggsp);
    gemm_mma_kernel<<<gemm_grid, 256>>>(aggsp, hsap, 256, 8, wl1p, wr1p, bl1,
                                        nullptr, hsbp, 1);

    // ---- layer 2: 1-term, agg hi-only, fp32 output ----
    agg_split_hi_kernel<<<agg_blocks, 256>>>(hsbp, aggsp);
    gemm_mma_kernel<<<gemm_grid, 256>>>(aggsp, hsbp, 256, 8, wl2p, wr2p, bl2,
                                        out, nullptr, 0);
}

// round 15
// speedup vs baseline: 1.6063x; 1.0546x over previous
#include <cuda_runtime.h>
#include <cuda_fp16.h>
#include <cstdint>

#define NNODES 50000
#define NEDGES 600000

// ---------------- device scratch (no allocations allowed) ----------------
__device__ int   g_deg[NNODES];
__device__ int   g_off[NNODES + 1];
__device__ int   g_cur[NNODES];
__device__ int   g_srcsorted[NEDGES];

// fp16 planes (stored as ushort bits)
__device__ unsigned short g_xs  [NNODES * 256];   // x: [hi128|lo128] (lo unused, kept for layout)
__device__ unsigned short g_aggs[NNODES * 512];   // agg hi plane in [0,K)
__device__ unsigned short g_hsa [NNODES * 512];   // h0 hi plane
__device__ unsigned short g_hsb [NNODES * 512];   // h1 hi plane

// weight hi planes: [K, 256] row-major (rows = k); buffers oversized from split era
__device__ unsigned short g_Wl0s[256 * 256];
__device__ unsigned short g_Wr0s[256 * 256];
__device__ unsigned short g_Wl1s[512 * 256];
__device__ unsigned short g_Wr1s[512 * 256];
__device__ unsigned short g_Wl2s[512 * 256];
__device__ unsigned short g_Wr2s[512 * 256];

// ---------------- helpers ----------------
__device__ __forceinline__ unsigned short hfbits(float f) {
    __half h = __float2half_rn(f);
    return reinterpret_cast<unsigned short&>(h);
}
__device__ __forceinline__ uint32_t smem_u32(const void* p) {
    return (uint32_t)__cvta_generic_to_shared(p);
}
__device__ __forceinline__ void cp16(uint32_t dst, const void* src, int sz) {
    asm volatile("cp.async.cg.shared.global [%0], [%1], 16, %2;\n"
                 :: "r"(dst), "l"(src), "r"(sz));
}
__device__ __forceinline__ void cp_commit() {
    asm volatile("cp.async.commit_group;\n" ::: "memory");
}

#define LDSM4(R0, R1, R2, R3, ADDR) \
    asm volatile("ldmatrix.sync.aligned.m8n8.x4.shared.b16 {%0,%1,%2,%3}, [%4];" \
                 : "=r"(R0), "=r"(R1), "=r"(R2), "=r"(R3) : "r"(ADDR))
#define LDSM4T(R0, R1, R2, R3, ADDR) \
    asm volatile("ldmatrix.sync.aligned.m8n8.x4.trans.shared.b16 {%0,%1,%2,%3}, [%4];" \
                 : "=r"(R0), "=r"(R1), "=r"(R2), "=r"(R3) : "r"(ADDR))
#define MMA16816(D, A, B) \
    asm volatile("mma.sync.aligned.m16n8k16.row.col.f32.f16.f16.f32 " \
                 "{%0,%1,%2,%3},{%4,%5,%6,%7},{%8,%9},{%0,%1,%2,%3};" \
                 : "+f"((D)[0]), "+f"((D)[1]), "+f"((D)[2]), "+f"((D)[3]) \
                 : "r"((A)[0]), "r"((A)[1]), "r"((A)[2]), "r"((A)[3]), \
                   "r"((B)[0]), "r"((B)[1]))

// ---------------- CSR build ----------------
__global__ void zero_deg_kernel() {
    int i = blockIdx.x * blockDim.x + threadIdx.x;
    if (i < NNODES) g_deg[i] = 0;
}
__global__ void hist_kernel(const int* __restrict__ dst) {
    int e = blockIdx.x * blockDim.x + threadIdx.x;
    if (e < NEDGES) atomicAdd(&g_deg[dst[e]], 1);
}
__global__ void scan_kernel() {
    __shared__ int sums[1024];
    int t = threadIdx.x;
    const int n = NNODES;
    const int chunk = (n + 1023) / 1024;
    int begin = t * chunk;
    int end = begin + chunk; if (end > n) end = n;
    int s = 0;
    for (int i = begin; i < end; ++i) s += g_deg[i];
    sums[t] = s;
    __syncthreads();
    for (int ofs = 1; ofs < 1024; ofs <<= 1) {
        int v = (t >= ofs) ? sums[t - ofs] : 0;
        __syncthreads();
        sums[t] += v;
        __syncthreads();
    }
    int prefix = (t == 0) ? 0 : sums[t - 1];
    for (int i = begin; i < end; ++i) {
        g_off[i] = prefix;
        g_cur[i] = prefix;
        prefix += g_deg[i];
    }
    if (t == 1023) g_off[n] = NEDGES;
}
__global__ void fill_kernel(const int* __restrict__ src, const int* __restrict__ dst) {
    int e = blockIdx.x * blockDim.x + threadIdx.x;
    if (e < NEDGES) {
        int d = dst[e];
        int p = atomicAdd(&g_cur[d], 1);
        g_srcsorted[p] = src[e];
    }
}

// ---------------- conversion kernels (hi plane only) ----------------
__global__ void xhi_kernel(const float* __restrict__ x, unsigned short* __restrict__ out) {
    int i = blockIdx.x * blockDim.x + threadIdx.x;
    if (i >= NNODES * 128) return;
    int r = i >> 7, c = i & 127;
    out[r * 256 + c] = hfbits(x[i]);
}
// W [K,256] row-major -> out [K, 256] fp16 hi
__global__ void whi_kernel(const float* __restrict__ W, unsigned short* __restrict__ out, int total) {
    int i = blockIdx.x * blockDim.x + threadIdx.x;
    if (i >= total) return;
    out[i] = hfbits(W[i]);
}

// ---------------- aggregation (hi-plane gather, hi-only store) ----------------
__device__ __forceinline__ void hi_store4(float4 v, unsigned short* hip) {
    unsigned short h0 = hfbits(v.x), h1 = hfbits(v.y), h2 = hfbits(v.z), h3 = hfbits(v.w);
    uint2 hi = make_uint2((uint32_t)h0 | ((uint32_t)h1 << 16),
                          (uint32_t)h2 | ((uint32_t)h3 << 16));
    *(uint2*)hip = hi;
}

// layer 0: gather fp16 hi plane of x (D=128, row stride 256)
__global__ void agg_hi128_kernel(const unsigned short* __restrict__ hs,
                                 unsigned short* __restrict__ outs) {
    int warp = (blockIdx.x * blockDim.x + threadIdx.x) >> 5;
    if (warp >= NNODES) return;
    int lane = threadIdx.x & 31;
    int s = g_off[warp];
    int e = g_off[warp + 1];
    int cnt = e - s;
    float inv = 1.0f / (float)(cnt > 0 ? cnt : 1);
    int c0 = lane * 4;
    unsigned short* orow = outs + (size_t)warp * 256;

    float4 acc = make_float4(0.f, 0.f, 0.f, 0.f);
    for (int i = s; i < e; ++i) {
        int src = g_srcsorted[i];
        uint2 u = *(const uint2*)&hs[(size_t)src * 256 + c0];
        __half2 p;
        float2 f;
        reinterpret_cast<uint32_t&>(p) = u.x; f = __half22float2(p);
        acc.x += f.x; acc.y += f.y;
        reinterpret_cast<uint32_t&>(p) = u.y; f = __half22float2(p);
        acc.z += f.x; acc.w += f.y;
    }
    acc.x *= inv; acc.y *= inv; acc.z *= inv; acc.w *= inv;
    hi_store4(acc, orow + c0);
}

// layers 1/2: gather fp16 hi plane (D=256, row stride 512)
__global__ void agg_hi256_kernel(const unsigned short* __restrict__ hs,
                                 unsigned short* __restrict__ outs) {
    int warp = (blockIdx.x * blockDim.x + threadIdx.x) >> 5;
    if (warp >= NNODES) return;
    int lane = threadIdx.x & 31;
    int s = g_off[warp];
    int e = g_off[warp + 1];
    int cnt = e - s;
    float inv = 1.0f / (float)(cnt > 0 ? cnt : 1);
    int c0 = lane * 4;
    unsigned short* orow = outs + (size_t)warp * 512;

    float4 a0 = make_float4(0.f, 0.f, 0.f, 0.f);
    float4 a1 = make_float4(0.f, 0.f, 0.f, 0.f);
    for (int i = s; i < e; ++i) {
        int src = g_srcsorted[i];
        const unsigned short* row = hs + (size_t)src * 512;
        uint2 u0 = *(const uint2*)&row[c0];
        uint2 u1 = *(const uint2*)&row[c0 + 128];
        __half2 p;
        float2 f;
        reinterpret_cast<uint32_t&>(p) = u0.x; f = __half22float2(p);
        a0.x += f.x; a0.y += f.y;
        reinterpret_cast<uint32_t&>(p) = u0.y; f = __half22float2(p);
        a0.z += f.x; a0.w += f.y;
        reinterpret_cast<uint32_t&>(p) = u1.x; f = __half22float2(p);
        a1.x += f.x; a1.y += f.y;
        reinterpret_cast<uint32_t&>(p) = u1.y; f = __half22float2(p);
        a1.z += f.x; a1.w += f.y;
    }
    a0.x *= inv; a0.y *= inv; a0.z *= inv; a0.w *= inv;
    a1.x *= inv; a1.y *= inv; a1.z *= inv; a1.w *= inv;
    hi_store4(a0, orow + c0);
    hi_store4(a1, orow + 128 + c0);
}

// ---------------- fp16 MMA GEMM, 1-term (pure hi x hi), two passes ----------------
// A planes: [M, astride] fp16, hi cols [0,Kp). B: [Kp, 256] fp16 hi.
// nchunks = 2*cpp, cpp = Kp/32. Pass0 = A0@B0, pass1 = A1@B1, summed into acc.
// Epilogue: +bias, relu opt; writes Cout fp32 and/or Csplit hi plane.
__global__ void __launch_bounds__(256, 2)
gemm_mma_kernel(const unsigned short* __restrict__ A0,
                const unsigned short* __restrict__ A1,
                int Kp, int astride,
                const unsigned short* __restrict__ B0,
                const unsigned short* __restrict__ B1,
                const float* __restrict__ bias,
                float* __restrict__ Cout,
                unsigned short* __restrict__ Csplit,
                int relu) {
    constexpr int AP = 40;    // As row pad (fp16 elems)
    constexpr int BP = 136;   // Bs row pad
    __shared__ unsigned short As[2][128 * AP];
    __shared__ unsigned short Bs[2][32 * BP];

    const int tid = threadIdx.x;
    const int warp = tid >> 5;
    const int lane = tid & 31;
    const int warp_m = warp & 3;   // 4 warps of 32 rows
    const int warp_n = warp >> 2;  // 2 warps of 64 cols
    const int m0 = blockIdx.y * 128;
    const int n0 = blockIdx.x * 128;

    const int cpp = Kp >> 5;
    const int nchunks = 2 * cpp;

    float acc[2][8][4];
#pragma unroll
    for (int mt = 0; mt < 2; ++mt)
#pragma unroll
        for (int nt = 0; nt < 8; ++nt)
#pragma unroll
            for (int q = 0; q < 4; ++q) acc[mt][nt][q] = 0.f;

    uint32_t as_base[2] = { smem_u32(&As[0][0]), smem_u32(&As[1][0]) };
    uint32_t bs_base[2] = { smem_u32(&Bs[0][0]), smem_u32(&Bs[1][0]) };

    // ---- tile loader ----
    auto load_tile = [&](int c, int buf) {
        int pass = (c >= cpp) ? 1 : 0;
        int kb = (c - pass * cpp) << 5;
        const unsigned short* A = pass ? A1 : A0;
        const unsigned short* B = pass ? B1 : B0;
        // A tile: 128 rows x 32 cols
        {
            int r = tid >> 2;
            int kc = (tid & 3) << 3;
#pragma unroll
            for (int i = 0; i < 2; ++i) {
                int row = r + i * 64;
                int grow = m0 + row;
                int ok = grow < NNODES;
                const unsigned short* src = A + (size_t)(ok ? grow : 0) * astride + kb + kc;
                cp16(as_base[buf] + (row * AP + kc) * 2, src, ok ? 16 : 0);
            }
        }
        // B tile: 32 rows x 128 cols
        {
            int r = tid >> 4;
            int col = (tid & 15) << 3;
#pragma unroll
            for (int i = 0; i < 2; ++i) {
                int row = r + i * 16;
                const unsigned short* src = B + (size_t)(kb + row) * 256 + n0 + col;
                cp16(bs_base[buf] + (row * BP + col) * 2, src, 16);
            }
        }
        cp_commit();
    };

    load_tile(0, 0);

    for (int c = 0; c < nchunks; ++c) {
        if (c + 1 < nchunks) {
            load_tile(c + 1, (c + 1) & 1);
            asm volatile("cp.async.wait_group 1;\n" ::: "memory");
        } else {
            asm volatile("cp.async.wait_group 0;\n" ::: "memory");
        }
        __syncthreads();

        int buf = c & 1;
        uint32_t ab = as_base[buf];
        uint32_t bb = bs_base[buf];
#pragma unroll
        for (int k16 = 0; k16 < 32; k16 += 16) {
            uint32_t a[2][4];
#pragma unroll
            for (int mt = 0; mt < 2; ++mt) {
                int mrow = warp_m * 32 + mt * 16 + (lane & 15);
                int kc = k16 + ((lane >> 4) << 3);
                LDSM4(a[mt][0], a[mt][1], a[mt][2], a[mt][3], ab + (mrow * AP + kc) * 2);
            }
            uint32_t b[8][2];
#pragma unroll
            for (int p = 0; p < 4; ++p) {
                int brow2 = k16 + (lane & 15);
                int bcol = warp_n * 64 + p * 16 + ((lane >> 4) << 3);
                LDSM4T(b[2 * p][0], b[2 * p][1], b[2 * p + 1][0], b[2 * p + 1][1],
                       bb + (brow2 * BP + bcol) * 2);
            }
#pragma unroll
            for (int mt = 0; mt < 2; ++mt)
#pragma unroll
                for (int nt = 0; nt < 8; ++nt)
                    MMA16816(acc[mt][nt], a[mt], b[nt]);
        }
        __syncthreads();
    }

    // ---- epilogue (Csplit: hi plane only) ----
    int g = lane >> 2;
    int tg = lane & 3;
#pragma unroll
    for (int mt = 0; mt < 2; ++mt) {
#pragma unroll
        for (int nt = 0; nt < 8; ++nt) {
            int col = n0 + warp_n * 64 + nt * 8 + tg * 2;
            float b0 = bias[col], b1 = bias[col + 1];
            int r0 = m0 + warp_m * 32 + mt * 16 + g;
            int r1 = r0 + 8;
            float v0 = acc[mt][nt][0] + b0;
            float v1 = acc[mt][nt][1] + b1;
            float v2 = acc[mt][nt][2] + b0;
            float v3 = acc[mt][nt][3] + b1;
            if (relu) {
                v0 = v0 > 0.f ? v0 : 0.f;
                v1 = v1 > 0.f ? v1 : 0.f;
                v2 = v2 > 0.f ? v2 : 0.f;
                v3 = v3 > 0.f ? v3 : 0.f;
            }
            if (r0 < NNODES) {
                if (Cout) *(float2*)&Cout[(size_t)r0 * 256 + col] = make_float2(v0, v1);
                if (Csplit) {
                    unsigned short h0 = hfbits(v0), h1 = hfbits(v1);
                    *(uint32_t*)&Csplit[(size_t)r0 * 512 + col] =
                        (uint32_t)h0 | ((uint32_t)h1 << 16);
                }
            }
            if (r1 < NNODES) {
                if (Cout) *(float2*)&Cout[(size_t)r1 * 256 + col] = make_float2(v2, v3);
                if (Csplit) {
                    unsigned short h2 = hfbits(v2), h3 = hfbits(v3);
                    *(uint32_t*)&Csplit[(size_t)r1 * 512 + col] =
                        (uint32_t)h2 | ((uint32_t)h3 << 16);
                }
            }
        }
    }
}

// ---------------- launch ----------------
extern "C" void kernel_launch(void* const* d_in, const int* in_sizes, int n_in,
                              void* d_out, int out_size) {
    const float* x   = (const float*)d_in[0];
    const int*   ei  = (const int*)d_in[1];
    const float* Wl0 = (const float*)d_in[2];
    const float* bl0 = (const float*)d_in[3];
    const float* Wr0 = (const float*)d_in[4];
    const float* Wl1 = (const float*)d_in[5];
    const float* bl1 = (const float*)d_in[6];
    const float* Wr1 = (const float*)d_in[7];
    const float* Wl2 = (const float*)d_in[8];
    const float* bl2 = (const float*)d_in[9];
    const float* Wr2 = (const float*)d_in[10];
    float* out = (float*)d_out;

    const int* src = ei;
    const int* dst = ei + NEDGES;

    unsigned short *xsp, *aggsp, *hsap, *hsbp;
    unsigned short *wl0p, *wr0p, *wl1p, *wr1p, *wl2p, *wr2p;
    cudaGetSymbolAddress((void**)&xsp, g_xs);
    cudaGetSymbolAddress((void**)&aggsp, g_aggs);
    cudaGetSymbolAddress((void**)&hsap, g_hsa);
    cudaGetSymbolAddress((void**)&hsbp, g_hsb);
    cudaGetSymbolAddress((void**)&wl0p, g_Wl0s);
    cudaGetSymbolAddress((void**)&wr0p, g_Wr0s);
    cudaGetSymbolAddress((void**)&wl1p, g_Wl1s);
    cudaGetSymbolAddress((void**)&wr1p, g_Wr1s);
    cudaGetSymbolAddress((void**)&wl2p, g_Wl2s);
    cudaGetSymbolAddress((void**)&wr2p, g_Wr2s);

    // ---- CSR build ----
    zero_deg_kernel<<<(NNODES + 255) / 256, 256>>>();
    hist_kernel<<<(NEDGES + 255) / 256, 256>>>(dst);
    scan_kernel<<<1, 1024>>>();
    fill_kernel<<<(NEDGES + 255) / 256, 256>>>(src, dst);

    // ---- conversions (hi planes only) ----
    xhi_kernel<<<(NNODES * 128 + 255) / 256, 256>>>(x, xsp);
    whi_kernel<<<(128 * 256 + 255) / 256, 256>>>(Wl0, wl0p, 128 * 256);
    whi_kernel<<<(128 * 256 + 255) / 256, 256>>>(Wr0, wr0p, 128 * 256);
    whi_kernel<<<(256 * 256 + 255) / 256, 256>>>(Wl1, wl1p, 256 * 256);
    whi_kernel<<<(256 * 256 + 255) / 256, 256>>>(Wr1, wr1p, 256 * 256);
    whi_kernel<<<(256 * 256 + 255) / 256, 256>>>(Wl2, wl2p, 256 * 256);
    whi_kernel<<<(256 * 256 + 255) / 256, 256>>>(Wr2, wr2p, 256 * 256);

    dim3 gemm_grid(2, (NNODES + 127) / 128);
    int agg_blocks = (NNODES * 32 + 255) / 256;

    // ---- layer 0: Kp=128, agg from x hi plane ----
    agg_hi128_kernel<<<agg_blocks, 256>>>(xsp, aggsp);
    gemm_mma_kernel<<<gemm_grid, 256>>>(aggsp, xsp, 128, 256, wl0p, wr0p, bl0,
                                        nullptr, hsap, 1);

    // ---- layer 1: Kp=256 ----
    agg_hi256_kernel<<<agg_blocks, 256>>>(hsap, aggsp);
    gemm_mma_kernel<<<gemm_grid, 256>>>(aggsp, hsap, 256, 512, wl1p, wr1p, bl1,
                                        nullptr, hsbp, 1);

    // ---- layer 2: Kp=256, fp32 output ----
    agg_hi256_kernel<<<agg_blocks, 256>>>(hsbp, aggsp);
    gemm_mma_kernel<<<gemm_grid, 256>>>(aggsp, hsbp, 256, 512, wl2p, wr2p, bl2,
                                        out, nullptr, 0);
}